// round 11
// baseline (speedup 1.0000x reference)
#include <cuda_runtime.h>
#include <cuda_fp16.h>
#include <math.h>
#include <stdint.h>

// Problem constants
#define BB   4
#define MM   2048
#define DD   256
#define EE   1024
#define HH   8
#define DH   32
#define TD   768   // 3*DD

// ---------------------------------------------------------------------------
// Scratch (no cudaMalloc allowed)
// ---------------------------------------------------------------------------
__device__ __half g_qkvh  [BB * MM * TD];      // 12 MB (Q pre-scaled by 1/sqrt(dh)*log2e)
__device__ __half g_attnh [BB * MM * DD];      // 4 MB
__device__ __half g_attnph[BB * MM * DD];      // 4 MB
__device__ float  g_Sp    [2 * BB * EE * DD];  // 8 MB (split-K partials)
__device__ float  g_S     [BB * EE * DD];      // 4 MB
__device__ __half g_efh   [BB * EE * DD];      // 2 MB
__device__ float  g_ef2   [BB * EE * DD];      // 4 MB

// ---------------------------------------------------------------------------
// Helpers
// ---------------------------------------------------------------------------
__device__ __forceinline__ uint32_t f2h2(float a, float b) {
    __half2 h = __floats2half2_rn(a, b);
    return *reinterpret_cast<uint32_t*>(&h);
}

__device__ __forceinline__ void mma_f16(float* c, const uint32_t* a,
                                        uint32_t b0, uint32_t b1) {
    asm volatile(
        "mma.sync.aligned.m16n8k16.row.col.f32.f16.f16.f32 "
        "{%0,%1,%2,%3}, {%4,%5,%6,%7}, {%8,%9}, {%0,%1,%2,%3};\n"
        : "+f"(c[0]), "+f"(c[1]), "+f"(c[2]), "+f"(c[3])
        : "r"(a[0]), "r"(a[1]), "r"(a[2]), "r"(a[3]), "r"(b0), "r"(b1));
}

// non-transposed x2: B-fragment for row-major [n][k] tiles
__device__ __forceinline__ void ldsm2(uint32_t& b0, uint32_t& b1,
                                      uint32_t addr) {
    asm volatile("ldmatrix.sync.aligned.m8n8.x2.shared.b16 {%0,%1}, [%2];"
                 : "=r"(b0), "=r"(b1) : "r"(addr));
}

__device__ __forceinline__ void ldsm2t(uint32_t& b0, uint32_t& b1,
                                       uint32_t addr) {
    asm volatile("ldmatrix.sync.aligned.m8n8.x2.trans.shared.b16 {%0,%1}, [%2];"
                 : "=r"(b0), "=r"(b1) : "r"(addr));
}

__device__ __forceinline__ void ldsm4t(uint32_t* a, uint32_t addr) {
    asm volatile("ldmatrix.sync.aligned.m8n8.x4.trans.shared.b16 {%0,%1,%2,%3}, [%4];"
                 : "=r"(a[0]), "=r"(a[1]), "=r"(a[2]), "=r"(a[3]) : "r"(addr));
}

__device__ __forceinline__ uint32_t smem_u32(const void* p) {
    uint32_t a;
    asm("{ .reg .u64 t; cvta.to.shared.u64 t, %1; cvt.u32.u64 %0, t; }"
        : "=r"(a) : "l"(p));
    return a;
}

// ---------------------------------------------------------------------------
// fp16 NT GEMM: C[M,N] = A[M,K] @ B[N,K]^T (+bias), fp32 accumulate.
// BM=128, BK=32, BN template. 256 threads, 8 warps (4m x 2n).
// B-fragments via ldmatrix.x2 (non-trans).
// Columns c < scale_cols get multiplied by qs after bias (Q pre-scaling).
// ---------------------------------------------------------------------------
template <int BN, typename TA, typename TC>
__global__ __launch_bounds__(256) void hgemm_nt(
    const TA* __restrict__ A, const float* __restrict__ W,
    const float* __restrict__ bias, TC* __restrict__ C,
    int K, int lda, int ldc, int scale_cols, float qs)
{
    constexpr int NF = BN / 16;
    __shared__ uint32_t As[2][128][20];
    __shared__ uint32_t Bs[2][BN][20];

    const int tid = threadIdx.x, lane = tid & 31, wid = tid >> 5;
    const int wm = (wid >> 1) * 32, wn = (wid & 1) * (BN / 2);
    const int m0 = blockIdx.y * 128, n0 = blockIdx.x * BN;

    const int ar = tid >> 1;
    constexpr int TPB = 256 / BN;
    constexpr int BH  = 32 / TPB;
    const int br = tid / TPB;

    const TA* Ap = A + (size_t)(m0 + ar) * lda + (tid & 1) * 16;
    const float* Wp = W + (size_t)(n0 + br) * K + (tid % TPB) * BH;

    const uint32_t bsb = smem_u32(Bs);

    float4 paf[4], pbf[BH / 4];
    uint4  pah[2];

    auto loadA = [&](int k0) {
        if constexpr (sizeof(TA) == 4) {
            const float* p = (const float*)Ap + k0;
            #pragma unroll
            for (int i = 0; i < 4; i++) paf[i] = *(const float4*)(p + i * 4);
        } else {
            const __half* p = (const __half*)Ap + k0;
            pah[0] = *(const uint4*)p;
            pah[1] = *(const uint4*)(p + 8);
        }
    };
    auto storeA = [&](int s) {
        uint32_t* d = &As[s][ar][(tid & 1) * 8];
        if constexpr (sizeof(TA) == 4) {
            #pragma unroll
            for (int i = 0; i < 4; i++) {
                d[2 * i]     = f2h2(paf[i].x, paf[i].y);
                d[2 * i + 1] = f2h2(paf[i].z, paf[i].w);
            }
        } else {
            *(uint4*)d = pah[0];
            *(uint4*)(d + 4) = pah[1];
        }
    };
    auto loadB = [&](int k0) {
        const float* p = Wp + k0;
        #pragma unroll
        for (int i = 0; i < BH / 4; i++) pbf[i] = *(const float4*)(p + i * 4);
    };
    auto storeB = [&](int s) {
        uint32_t* d = &Bs[s][br][(tid % TPB) * (BH / 2)];
        #pragma unroll
        for (int i = 0; i < BH / 4; i++) {
            d[2 * i]     = f2h2(pbf[i].x, pbf[i].y);
            d[2 * i + 1] = f2h2(pbf[i].z, pbf[i].w);
        }
    };

    float acc[2][NF][4] = {};
    loadA(0); loadB(0);

    const int nk = K >> 5;
    for (int t = 0; t < nk; t++) {
        const int s = t & 1;
        storeA(s); storeB(s);
        if (t + 1 < nk) { loadA((t + 1) * 32); loadB((t + 1) * 32); }
        __syncthreads();

        #pragma unroll
        for (int kk = 0; kk < 2; kk++) {
            uint32_t a[2][4];
            const int c = kk * 8 + (lane & 3);
            #pragma unroll
            for (int mi = 0; mi < 2; mi++) {
                const int r = wm + mi * 16 + (lane >> 2);
                a[mi][0] = As[s][r][c];     a[mi][1] = As[s][r + 8][c];
                a[mi][2] = As[s][r][c + 4]; a[mi][3] = As[s][r + 8][c + 4];
            }
            #pragma unroll
            for (int ni = 0; ni < NF; ni++) {
                uint32_t baddr = bsb +
                    (((s * BN + wn + ni * 8 + (lane & 7)) * 20 + kk * 8) << 2) +
                    ((lane & 8) << 1);
                uint32_t b0, b1;
                ldsm2(b0, b1, baddr);
                #pragma unroll
                for (int mi = 0; mi < 2; mi++)
                    mma_f16(acc[mi][ni], a[mi], b0, b1);
            }
        }
    }

    #pragma unroll
    for (int mi = 0; mi < 2; mi++) {
        #pragma unroll
        for (int ni = 0; ni < NF; ni++) {
            const int r = m0 + wm + mi * 16 + (lane >> 2);
            const int c = n0 + wn + ni * 8 + 2 * (lane & 3);
            float b0 = bias ? bias[c] : 0.0f;
            float b1 = bias ? bias[c + 1] : 0.0f;
            float v0 = acc[mi][ni][0] + b0, v1 = acc[mi][ni][1] + b1;
            float v2 = acc[mi][ni][2] + b0, v3 = acc[mi][ni][3] + b1;
            if (c < scale_cols) { v0 *= qs; v1 *= qs; v2 *= qs; v3 *= qs; }
            if constexpr (sizeof(TC) == 2) {
                *(__half2*)&C[(size_t)r * ldc + c]       = __floats2half2_rn(v0, v1);
                *(__half2*)&C[(size_t)(r + 8) * ldc + c] = __floats2half2_rn(v2, v3);
            } else {
                *(float2*)&C[(size_t)r * ldc + c]       = make_float2(v0, v1);
                *(float2*)&C[(size_t)(r + 8) * ldc + c] = make_float2(v2, v3);
            }
        }
    }
}

// ---------------------------------------------------------------------------
// fp16 TN GEMM (for S): Sp[z][e][d] = sum_m inc[b][m][e] * attnph[b][m][d]
// ldmatrix.trans fragments. BM=128(e), BN=64(d), BK=32(m), 256 threads.
// Split-K x2 over m (1024 each): z = blockIdx.z, bz=z>>1, sp=z&1.
// ---------------------------------------------------------------------------
__global__ __launch_bounds__(256) void sgemm_tn_h(
    const float* __restrict__ inc, const __half* __restrict__ Bh,
    float* __restrict__ Sp)
{
    __shared__ uint32_t As[2][32][68];   // [m][e-pairs]
    __shared__ uint32_t Bs[2][32][36];   // [m][d-pairs]

    const int tid = threadIdx.x, lane = tid & 31, wid = tid >> 5;
    const int wm = (wid >> 1) * 32, wn = (wid & 1) * 32;
    const int z = blockIdx.z, bz = z >> 1, sp = z & 1;
    const int e0 = blockIdx.y * 128, d0 = blockIdx.x * 64;
    const float*  Ab = inc + (size_t)bz * MM * EE + (size_t)(sp * 1024) * EE;
    const __half* Bb = Bh  + (size_t)bz * MM * DD + (size_t)(sp * 1024) * DD;

    const int am = tid >> 3;
    const float*  Apt = Ab + (size_t)am * EE + e0 + (tid & 7) * 16;
    const __half* Bpt = Bb + (size_t)am * DD + d0 + (tid & 7) * 8;

    float4 pa[4];
    uint4  pb;
    auto loadT = [&](int k0) {
        const float* p = Apt + (size_t)k0 * EE;
        #pragma unroll
        for (int i = 0; i < 4; i++) pa[i] = *(const float4*)(p + i * 4);
        pb = *(const uint4*)(Bpt + (size_t)k0 * DD);
    };
    auto storeT = [&](int s) {
        uint32_t* da = &As[s][am][(tid & 7) * 8];
        #pragma unroll
        for (int i = 0; i < 4; i++) {
            da[2 * i]     = f2h2(pa[i].x, pa[i].y);
            da[2 * i + 1] = f2h2(pa[i].z, pa[i].w);
        }
        *(uint4*)&Bs[s][am][(tid & 7) * 4] = pb;
    };

    const uint32_t asb = smem_u32(As), bsb = smem_u32(Bs);

    float acc[2][4][4] = {};
    loadT(0);

    for (int t = 0; t < 32; t++) {   // 1024 / 32
        const int s = t & 1;
        storeT(s);
        if (t + 1 < 32) loadT((t + 1) * 32);
        __syncthreads();

        #pragma unroll
        for (int kk = 0; kk < 2; kk++) {
            uint32_t a[2][4];
            #pragma unroll
            for (int mi = 0; mi < 2; mi++) {
                const int mrow = kk * 16 + (lane & 7) + ((lane & 16) >> 1);
                const int ecol = wm + mi * 16 + (lane & 8);
                uint32_t addr = asb + (((s * 32 + mrow) * 68 + (ecol >> 1)) << 2);
                ldsm4t(a[mi], addr);
            }
            #pragma unroll
            for (int ni = 0; ni < 4; ni++) {
                const int mrow = kk * 16 + (lane & 15);
                uint32_t addr = bsb + (((s * 32 + mrow) * 36 + (wn >> 1) + ni * 4) << 2);
                uint32_t b0, b1;
                ldsm2t(b0, b1, addr);
                #pragma unroll
                for (int mi = 0; mi < 2; mi++)
                    mma_f16(acc[mi][ni], a[mi], b0, b1);
            }
        }
    }

    float* Sb = Sp + (size_t)z * EE * DD;
    #pragma unroll
    for (int mi = 0; mi < 2; mi++) {
        #pragma unroll
        for (int ni = 0; ni < 4; ni++) {
            const int e = e0 + wm + mi * 16 + (lane >> 2);
            const int d = d0 + wn + ni * 8 + 2 * (lane & 3);
            *(float2*)&Sb[(size_t)e * DD + d] =
                make_float2(acc[mi][ni][0], acc[mi][ni][1]);
            *(float2*)&Sb[(size_t)(e + 8) * DD + d] =
                make_float2(acc[mi][ni][2], acc[mi][ni][3]);
        }
    }
}

// Reduce 2 split-K partials ordered [b][sp]: S[b] = Sp[2b] + Sp[2b+1]
__global__ __launch_bounds__(256) void reduce2(
    const float4* __restrict__ Sp, float4* __restrict__ S)
{
    const size_t per = (size_t)EE * DD / 4;
    size_t i = (size_t)blockIdx.x * 256 + threadIdx.x;
    if (i >= (size_t)BB * per) return;
    size_t b = i / per, j = i - b * per;
    const float4* p = Sp + 2 * b * per + j;
    float4 a = p[0], x = p[per];
    float4 r;
    r.x = a.x + x.x; r.y = a.y + x.y; r.z = a.z + x.z; r.w = a.w + x.w;
    S[i] = r;
}

// ---------------------------------------------------------------------------
// Flash attention, fp16 in/out, base-2 online softmax (Q pre-scaled by
// 1/sqrt(dh)*log2e in the QKV epilogue → exp == exp2, bare MUFU.EX2).
// 128 q-rows per block, 256 threads / 8 warps. K-fragments via ldmatrix.x2.
// ---------------------------------------------------------------------------
__global__ __launch_bounds__(256) void flash_h(
    const __half* __restrict__ qkv, __half* __restrict__ o)
{
    __shared__ uint32_t Ks[2][64][20];
    __shared__ uint32_t Vs[2][64][20];
    __shared__ uint32_t Ps[128 * 36];

    const int bh = blockIdx.y;
    const int b = bh >> 3, h = bh & 7;
    const int m0 = blockIdx.x * 128;
    const int tid = threadIdx.x;
    const int lane = tid & 31;
    const int w16 = (tid >> 5) * 16;

    const size_t base = (size_t)(b * MM) * TD + h * DH;

    // ---- stage Q (already scaled fp16) into Ps scratch (pitch 20 u32) ----
    {
        const int r = tid >> 1;
        const __half* qp = &qkv[base + (size_t)(m0 + r) * TD + (tid & 1) * 16];
        uint32_t* d = &Ps[r * 20 + (tid & 1) * 8];
        *(uint4*)d       = *(const uint4*)qp;
        *(uint4*)(d + 4) = *(const uint4*)(qp + 8);
    }
    __syncthreads();
    uint32_t qa[2][4];
    #pragma unroll
    for (int kk = 0; kk < 2; kk++) {
        const int r = w16 + (lane >> 2), c = kk * 8 + (lane & 3);
        qa[kk][0] = Ps[r * 20 + c];        qa[kk][1] = Ps[(r + 8) * 20 + c];
        qa[kk][2] = Ps[r * 20 + c + 4];    qa[kk][3] = Ps[(r + 8) * 20 + c + 4];
    }
    __syncthreads();

    const uint32_t vsb = smem_u32(Vs), ksb = smem_u32(Ks);

    float O[4][4] = {};
    float mr0 = -1e30f, mr1 = -1e30f, l0 = 0.0f, l1 = 0.0f;

    const int rk = tid >> 2, ck = (tid & 3) * 8;
    uint4 ku, vu;
    {
        const __half* kp = &qkv[base + (size_t)rk * TD + 256 + ck];
        ku = *(const uint4*)kp;
        vu = *(const uint4*)(kp + 256);
    }

    const int ntile = MM / 64;
    for (int t = 0; t < ntile; t++) {
        const int s = t & 1;
        *(uint4*)&Ks[s][rk][(tid & 3) * 4] = ku;
        *(uint4*)&Vs[s][rk][(tid & 3) * 4] = vu;
        if (t + 1 < ntile) {
            const __half* kp = &qkv[base + (size_t)((t + 1) * 64 + rk) * TD + 256 + ck];
            ku = *(const uint4*)kp;
            vu = *(const uint4*)(kp + 256);
        }
        __syncthreads();

        // ---- S = Q @ K^T (K-fragments via ldmatrix.x2 non-trans) ----
        float sa[8][4] = {};
        #pragma unroll
        for (int j = 0; j < 8; j++) {
            #pragma unroll
            for (int kk = 0; kk < 2; kk++) {
                uint32_t baddr = ksb +
                    (((s * 64 + j * 8 + (lane & 7)) * 20 + kk * 8) << 2) +
                    ((lane & 8) << 1);
                uint32_t b0, b1;
                ldsm2(b0, b1, baddr);
                mma_f16(sa[j], qa[kk], b0, b1);
            }
        }

        // ---- online softmax (base 2) ----
        float mx0 = -1e30f, mx1 = -1e30f;
        #pragma unroll
        for (int j = 0; j < 8; j++) {
            mx0 = fmaxf(mx0, fmaxf(sa[j][0], sa[j][1]));
            mx1 = fmaxf(mx1, fmaxf(sa[j][2], sa[j][3]));
        }
        mx0 = fmaxf(mx0, __shfl_xor_sync(0xFFFFFFFFu, mx0, 1));
        mx0 = fmaxf(mx0, __shfl_xor_sync(0xFFFFFFFFu, mx0, 2));
        mx1 = fmaxf(mx1, __shfl_xor_sync(0xFFFFFFFFu, mx1, 1));
        mx1 = fmaxf(mx1, __shfl_xor_sync(0xFFFFFFFFu, mx1, 2));

        float mn0 = fmaxf(mr0, mx0), mn1 = fmaxf(mr1, mx1);
        float al0 = exp2f(mr0 - mn0), al1 = exp2f(mr1 - mn1);
        mr0 = mn0; mr1 = mn1;

        float s0 = 0.0f, s1 = 0.0f;
        const int pr = w16 + (lane >> 2);
        #pragma unroll
        for (int j = 0; j < 8; j++) {
            float p00 = exp2f(sa[j][0] - mn0);
            float p01 = exp2f(sa[j][1] - mn0);
            float p10 = exp2f(sa[j][2] - mn1);
            float p11 = exp2f(sa[j][3] - mn1);
            s0 += p00 + p01; s1 += p10 + p11;
            const int pc = j * 4 + (lane & 3);
            Ps[pr * 36 + pc]       = f2h2(p00, p01);
            Ps[(pr + 8) * 36 + pc] = f2h2(p10, p11);
        }
        s0 += __shfl_xor_sync(0xFFFFFFFFu, s0, 1);
        s0 += __shfl_xor_sync(0xFFFFFFFFu, s0, 2);
        s1 += __shfl_xor_sync(0xFFFFFFFFu, s1, 1);
        s1 += __shfl_xor_sync(0xFFFFFFFFu, s1, 2);
        l0 = l0 * al0 + s0;
        l1 = l1 * al1 + s1;
        #pragma unroll
        for (int ni = 0; ni < 4; ni++) {
            O[ni][0] *= al0; O[ni][1] *= al0;
            O[ni][2] *= al1; O[ni][3] *= al1;
        }
        __syncwarp();

        // ---- O += P @ V ----
        #pragma unroll
        for (int kc = 0; kc < 4; kc++) {
            uint32_t pa[4];
            const int c = kc * 8 + (lane & 3);
            pa[0] = Ps[pr * 36 + c];       pa[1] = Ps[(pr + 8) * 36 + c];
            pa[2] = Ps[pr * 36 + c + 4];   pa[3] = Ps[(pr + 8) * 36 + c + 4];
            const int vrow = kc * 16 + (lane & 15);
            #pragma unroll
            for (int ni = 0; ni < 4; ni++) {
                uint32_t addr = vsb + ((s * 64 + vrow) * 20 + ni * 4) * 4;
                uint32_t b0, b1;
                ldsm2t(b0, b1, addr);
                mma_f16(O[ni], pa, b0, b1);
            }
        }
    }

    const float inv0 = 1.0f / l0, inv1 = 1.0f / l1;
    #pragma unroll
    for (int ni = 0; ni < 4; ni++) {
        const int row = m0 + w16 + (lane >> 2);
        const int col = h * DH + ni * 8 + 2 * (lane & 3);
        size_t off = ((size_t)(b * MM) + row) * DD + col;
        *(__half2*)&o[off] = __floats2half2_rn(O[ni][0] * inv0, O[ni][1] * inv0);
        *(__half2*)&o[off + 8 * DD] =
            __floats2half2_rn(O[ni][2] * inv1, O[ni][3] * inv1);
    }
}

// ---------------------------------------------------------------------------
// Column softmax over e + multiply:  ef = half(S * softmax_e(S))
// ---------------------------------------------------------------------------
__global__ __launch_bounds__(256) void col_softmax_mul(
    const float* __restrict__ S, __half* __restrict__ ef)
{
    const int b  = blockIdx.y;
    const int d0 = blockIdx.x * 64;
    const int dx = threadIdx.x & 63, ry = threadIdx.x >> 6;
    const float* Sb = S  + (size_t)b * EE * DD + d0 + dx;
    __half*      Eb = ef + (size_t)b * EE * DD + d0 + dx;

    __shared__ float red[4][64];

    float m = -1e30f;
    for (int e = ry; e < EE; e += 4) m = fmaxf(m, Sb[(size_t)e * DD]);
    red[ry][dx] = m;
    __syncthreads();
    m = fmaxf(fmaxf(red[0][dx], red[1][dx]), fmaxf(red[2][dx], red[3][dx]));
    __syncthreads();

    float s = 0.0f;
    for (int e = ry; e < EE; e += 4) s += __expf(Sb[(size_t)e * DD] - m);
    red[ry][dx] = s;
    __syncthreads();
    s = red[0][dx] + red[1][dx] + red[2][dx] + red[3][dx];
    float inv = 1.0f / s;

    for (int e = ry; e < EE; e += 4) {
        float v = Sb[(size_t)e * DD];
        Eb[(size_t)e * DD] = __float2half(v * __expf(v - m) * inv);
    }
}

// ---------------------------------------------------------------------------
// LayerNorm (dim 256) + residual mix:  out = (1+alpha)*prev + (1-alpha)*LN(x)
// ---------------------------------------------------------------------------
__global__ __launch_bounds__(256) void ln_res(
    const float* __restrict__ ef2, const float* __restrict__ prev,
    const float* __restrict__ gamma, const float* __restrict__ beta,
    const float* __restrict__ alphap, float* __restrict__ out)
{
    const int row = blockIdx.x;
    const int c = threadIdx.x;
    const size_t off = (size_t)row * DD + c;

    float x = ef2[off];
    float s = x, q = x * x;
    #pragma unroll
    for (int o2 = 16; o2 > 0; o2 >>= 1) {
        s += __shfl_down_sync(0xFFFFFFFFu, s, o2);
        q += __shfl_down_sync(0xFFFFFFFFu, q, o2);
    }
    __shared__ float rs[8], rq[8], mv[2];
    int w = c >> 5, l = c & 31;
    if (l == 0) { rs[w] = s; rq[w] = q; }
    __syncthreads();
    if (c == 0) {
        float S2 = 0.0f, Q2 = 0.0f;
        #pragma unroll
        for (int i = 0; i < 8; i++) { S2 += rs[i]; Q2 += rq[i]; }
        float mean = S2 * (1.0f / 256.0f);
        float var  = Q2 * (1.0f / 256.0f) - mean * mean;
        mv[0] = mean;
        mv[1] = rsqrtf(var + 1e-5f);
    }
    __syncthreads();

    float n = (x - mv[0]) * mv[1] * gamma[c] + beta[c];
    float a = *alphap;
    float p = prev[off];
    out[off] = (1.0f + a) * p + (1.0f - a) * n;
}

// ---------------------------------------------------------------------------
// Launch
// ---------------------------------------------------------------------------
extern "C" void kernel_launch(void* const* d_in, const int* in_sizes, int n_in,
                              void* d_out, int out_size)
{
    const float* feat = (const float*)d_in[0];
    const float* inc  = (const float*)d_in[1];
    const float* prev = (const float*)d_in[2];
    const float* ipw  = (const float*)d_in[3];
    const float* ipb  = (const float*)d_in[4];
    const float* opw  = (const float*)d_in[5];
    const float* opb  = (const float*)d_in[6];
    const float* pw   = (const float*)d_in[7];
    const float* gam  = (const float*)d_in[8];
    const float* bet  = (const float*)d_in[9];
    const float* alp  = (const float*)d_in[10];
    float* out = (float*)d_out;

    __half *qkvh, *attnh, *attnph, *efh;
    float *Sp, *Sb, *ef2;
    cudaGetSymbolAddress((void**)&qkvh,   g_qkvh);
    cudaGetSymbolAddress((void**)&attnh,  g_attnh);
    cudaGetSymbolAddress((void**)&attnph, g_attnph);
    cudaGetSymbolAddress((void**)&Sp,     g_Sp);
    cudaGetSymbolAddress((void**)&Sb,     g_S);
    cudaGetSymbolAddress((void**)&efh,    g_efh);
    cudaGetSymbolAddress((void**)&ef2,    g_ef2);

    // 1/sqrt(32) * log2(e): base-2 softmax absorbed into Q scaling
    const float qscale = 0.17677669529663689f * 1.4426950408889634f;

    // 1. QKV projection -> fp16, Q third pre-scaled
    hgemm_nt<128, float, __half>
        <<<dim3(TD / 128, (BB * MM) / 128), 256>>>(
            feat, ipw, ipb, qkvh, DD, DD, TD, DD, qscale);

    // 2. flash attention (fp16 in/out, base-2 softmax)
    flash_h<<<dim3(MM / 128, BB * HH), 256>>>(qkvh, attnh);

    // 3. out projection -> fp16 attnph
    hgemm_nt<64, __half, __half>
        <<<dim3(DD / 64, (BB * MM) / 128), 256>>>(
            attnh, opw, opb, attnph, DD, DD, DD, 0, 1.0f);

    // 4. S = inc^T @ attnph  (TN fp16, split-K x2) + reduce
    sgemm_tn_h<<<dim3(DD / 64, EE / 128, BB * 2), 256>>>(inc, attnph, Sp);
    reduce2<<<(BB * EE * DD / 4 + 255) / 256, 256>>>((const float4*)Sp,
                                                     (float4*)Sb);

    // 5. ef = half(S * softmax_e(S))
    col_softmax_mul<<<dim3(DD / 64, BB), 256>>>(Sb, efh);

    // 6. ef2 = ef @ proj_w^T
    hgemm_nt<64, __half, float>
        <<<dim3(DD / 64, (BB * EE) / 128), 256>>>(
            efh, pw, nullptr, ef2, DD, DD, DD, 0, 1.0f);

    // 7. LayerNorm + residual mix
    ln_res<<<BB * EE, 256>>>(ef2, prev, gam, bet, alp, out);
}

// round 12
// speedup vs baseline: 1.0144x; 1.0144x over previous
#include <cuda_runtime.h>
#include <cuda_fp16.h>
#include <math.h>
#include <stdint.h>

// Problem constants
#define BB   4
#define MM   2048
#define DD   256
#define EE   1024
#define HH   8
#define DH   32
#define TD   768   // 3*DD

// ---------------------------------------------------------------------------
// Scratch (no cudaMalloc allowed)
// ---------------------------------------------------------------------------
__device__ __half g_qkvh  [BB * MM * TD];      // 12 MB (Q pre-scaled by 1/sqrt(dh)*log2e)
__device__ __half g_attnh [BB * MM * DD];      // 4 MB
__device__ __half g_attnph[BB * MM * DD];      // 4 MB
__device__ float  g_Sp    [4 * BB * EE * DD];  // 16 MB (split-K partials)
__device__ float  g_S     [BB * EE * DD];      // 4 MB
__device__ __half g_efh   [BB * EE * DD];      // 2 MB
__device__ float  g_ef2   [BB * EE * DD];      // 4 MB

// ---------------------------------------------------------------------------
// Helpers
// ---------------------------------------------------------------------------
__device__ __forceinline__ uint32_t f2h2(float a, float b) {
    __half2 h = __floats2half2_rn(a, b);
    return *reinterpret_cast<uint32_t*>(&h);
}

// bare MUFU.EX2 — guaranteed single-instruction exp2
__device__ __forceinline__ float ex2(float x) {
    float r;
    asm("ex2.approx.f32 %0, %1;" : "=f"(r) : "f"(x));
    return r;
}

__device__ __forceinline__ void mma_f16(float* c, const uint32_t* a,
                                        uint32_t b0, uint32_t b1) {
    asm volatile(
        "mma.sync.aligned.m16n8k16.row.col.f32.f16.f16.f32 "
        "{%0,%1,%2,%3}, {%4,%5,%6,%7}, {%8,%9}, {%0,%1,%2,%3};\n"
        : "+f"(c[0]), "+f"(c[1]), "+f"(c[2]), "+f"(c[3])
        : "r"(a[0]), "r"(a[1]), "r"(a[2]), "r"(a[3]), "r"(b0), "r"(b1));
}

__device__ __forceinline__ void ldsm2t(uint32_t& b0, uint32_t& b1,
                                       uint32_t addr) {
    asm volatile("ldmatrix.sync.aligned.m8n8.x2.trans.shared.b16 {%0,%1}, [%2];"
                 : "=r"(b0), "=r"(b1) : "r"(addr));
}

__device__ __forceinline__ void ldsm4t(uint32_t* a, uint32_t addr) {
    asm volatile("ldmatrix.sync.aligned.m8n8.x4.trans.shared.b16 {%0,%1,%2,%3}, [%4];"
                 : "=r"(a[0]), "=r"(a[1]), "=r"(a[2]), "=r"(a[3]) : "r"(addr));
}

__device__ __forceinline__ uint32_t smem_u32(const void* p) {
    uint32_t a;
    asm("{ .reg .u64 t; cvta.to.shared.u64 t, %1; cvt.u32.u64 %0, t; }"
        : "=r"(a) : "l"(p));
    return a;
}

// ---------------------------------------------------------------------------
// fp16 NT GEMM: C[M,N] = A[M,K] @ B[N,K]^T (+bias), fp32 accumulate.
// BM=128, BK=32, BN template. 256 threads, 8 warps (4m x 2n).
// Columns c < scale_cols get multiplied by qs after bias (Q pre-scaling).
// (R10 version — scalar-LDS fragments.)
// ---------------------------------------------------------------------------
template <int BN, typename TA, typename TC>
__global__ __launch_bounds__(256) void hgemm_nt(
    const TA* __restrict__ A, const float* __restrict__ W,
    const float* __restrict__ bias, TC* __restrict__ C,
    int K, int lda, int ldc, int scale_cols, float qs)
{
    constexpr int NF = BN / 16;
    __shared__ uint32_t As[2][128][20];
    __shared__ uint32_t Bs[2][BN][20];

    const int tid = threadIdx.x, lane = tid & 31, wid = tid >> 5;
    const int wm = (wid >> 1) * 32, wn = (wid & 1) * (BN / 2);
    const int m0 = blockIdx.y * 128, n0 = blockIdx.x * BN;

    const int ar = tid >> 1;
    constexpr int TPB = 256 / BN;
    constexpr int BH  = 32 / TPB;
    const int br = tid / TPB;

    const TA* Ap = A + (size_t)(m0 + ar) * lda + (tid & 1) * 16;
    const float* Wp = W + (size_t)(n0 + br) * K + (tid % TPB) * BH;

    float4 paf[4], pbf[BH / 4];
    uint4  pah[2];

    auto loadA = [&](int k0) {
        if constexpr (sizeof(TA) == 4) {
            const float* p = (const float*)Ap + k0;
            #pragma unroll
            for (int i = 0; i < 4; i++) paf[i] = *(const float4*)(p + i * 4);
        } else {
            const __half* p = (const __half*)Ap + k0;
            pah[0] = *(const uint4*)p;
            pah[1] = *(const uint4*)(p + 8);
        }
    };
    auto storeA = [&](int s) {
        uint32_t* d = &As[s][ar][(tid & 1) * 8];
        if constexpr (sizeof(TA) == 4) {
            #pragma unroll
            for (int i = 0; i < 4; i++) {
                d[2 * i]     = f2h2(paf[i].x, paf[i].y);
                d[2 * i + 1] = f2h2(paf[i].z, paf[i].w);
            }
        } else {
            *(uint4*)d = pah[0];
            *(uint4*)(d + 4) = pah[1];
        }
    };
    auto loadB = [&](int k0) {
        const float* p = Wp + k0;
        #pragma unroll
        for (int i = 0; i < BH / 4; i++) pbf[i] = *(const float4*)(p + i * 4);
    };
    auto storeB = [&](int s) {
        uint32_t* d = &Bs[s][br][(tid % TPB) * (BH / 2)];
        #pragma unroll
        for (int i = 0; i < BH / 4; i++) {
            d[2 * i]     = f2h2(pbf[i].x, pbf[i].y);
            d[2 * i + 1] = f2h2(pbf[i].z, pbf[i].w);
        }
    };

    float acc[2][NF][4] = {};
    loadA(0); loadB(0);

    const int nk = K >> 5;
    for (int t = 0; t < nk; t++) {
        const int s = t & 1;
        storeA(s); storeB(s);
        if (t + 1 < nk) { loadA((t + 1) * 32); loadB((t + 1) * 32); }
        __syncthreads();

        #pragma unroll
        for (int kk = 0; kk < 2; kk++) {
            uint32_t a[2][4];
            const int c = kk * 8 + (lane & 3);
            #pragma unroll
            for (int mi = 0; mi < 2; mi++) {
                const int r = wm + mi * 16 + (lane >> 2);
                a[mi][0] = As[s][r][c];     a[mi][1] = As[s][r + 8][c];
                a[mi][2] = As[s][r][c + 4]; a[mi][3] = As[s][r + 8][c + 4];
            }
            #pragma unroll
            for (int ni = 0; ni < NF; ni++) {
                const int n = wn + ni * 8 + (lane >> 2);
                uint32_t b0 = Bs[s][n][c], b1 = Bs[s][n][c + 4];
                #pragma unroll
                for (int mi = 0; mi < 2; mi++)
                    mma_f16(acc[mi][ni], a[mi], b0, b1);
            }
        }
    }

    #pragma unroll
    for (int mi = 0; mi < 2; mi++) {
        #pragma unroll
        for (int ni = 0; ni < NF; ni++) {
            const int r = m0 + wm + mi * 16 + (lane >> 2);
            const int c = n0 + wn + ni * 8 + 2 * (lane & 3);
            float b0 = bias ? bias[c] : 0.0f;
            float b1 = bias ? bias[c + 1] : 0.0f;
            float v0 = acc[mi][ni][0] + b0, v1 = acc[mi][ni][1] + b1;
            float v2 = acc[mi][ni][2] + b0, v3 = acc[mi][ni][3] + b1;
            if (c < scale_cols) { v0 *= qs; v1 *= qs; v2 *= qs; v3 *= qs; }
            if constexpr (sizeof(TC) == 2) {
                *(__half2*)&C[(size_t)r * ldc + c]       = __floats2half2_rn(v0, v1);
                *(__half2*)&C[(size_t)(r + 8) * ldc + c] = __floats2half2_rn(v2, v3);
            } else {
                *(float2*)&C[(size_t)r * ldc + c]       = make_float2(v0, v1);
                *(float2*)&C[(size_t)(r + 8) * ldc + c] = make_float2(v2, v3);
            }
        }
    }
}

// ---------------------------------------------------------------------------
// fp16 TN GEMM (for S): Sp[z][e][d] = sum_m inc[b][m][e] * attnph[b][m][d]
// ldmatrix.trans fragments. BM=128(e), BN=64(d), BK=32(m), 256 threads.
// Split-K x4 over m (512 each): z = blockIdx.z, bz=z>>2, sp=z&3.  (R10 version)
// ---------------------------------------------------------------------------
__global__ __launch_bounds__(256) void sgemm_tn_h(
    const float* __restrict__ inc, const __half* __restrict__ Bh,
    float* __restrict__ Sp)
{
    __shared__ uint32_t As[2][32][68];   // [m][e-pairs]
    __shared__ uint32_t Bs[2][32][36];   // [m][d-pairs]

    const int tid = threadIdx.x, lane = tid & 31, wid = tid >> 5;
    const int wm = (wid >> 1) * 32, wn = (wid & 1) * 32;
    const int z = blockIdx.z, bz = z >> 2, sp = z & 3;
    const int e0 = blockIdx.y * 128, d0 = blockIdx.x * 64;
    const float*  Ab = inc + (size_t)bz * MM * EE + (size_t)(sp * 512) * EE;
    const __half* Bb = Bh  + (size_t)bz * MM * DD + (size_t)(sp * 512) * DD;

    const int am = tid >> 3;
    const float*  Apt = Ab + (size_t)am * EE + e0 + (tid & 7) * 16;
    const __half* Bpt = Bb + (size_t)am * DD + d0 + (tid & 7) * 8;

    float4 pa[4];
    uint4  pb;
    auto loadT = [&](int k0) {
        const float* p = Apt + (size_t)k0 * EE;
        #pragma unroll
        for (int i = 0; i < 4; i++) pa[i] = *(const float4*)(p + i * 4);
        pb = *(const uint4*)(Bpt + (size_t)k0 * DD);
    };
    auto storeT = [&](int s) {
        uint32_t* da = &As[s][am][(tid & 7) * 8];
        #pragma unroll
        for (int i = 0; i < 4; i++) {
            da[2 * i]     = f2h2(pa[i].x, pa[i].y);
            da[2 * i + 1] = f2h2(pa[i].z, pa[i].w);
        }
        *(uint4*)&Bs[s][am][(tid & 7) * 4] = pb;
    };

    const uint32_t asb = smem_u32(As), bsb = smem_u32(Bs);

    float acc[2][4][4] = {};
    loadT(0);

    for (int t = 0; t < 16; t++) {   // 512 / 32
        const int s = t & 1;
        storeT(s);
        if (t + 1 < 16) loadT((t + 1) * 32);
        __syncthreads();

        #pragma unroll
        for (int kk = 0; kk < 2; kk++) {
            uint32_t a[2][4];
            #pragma unroll
            for (int mi = 0; mi < 2; mi++) {
                const int mrow = kk * 16 + (lane & 7) + ((lane & 16) >> 1);
                const int ecol = wm + mi * 16 + (lane & 8);
                uint32_t addr = asb + (((s * 32 + mrow) * 68 + (ecol >> 1)) << 2);
                ldsm4t(a[mi], addr);
            }
            #pragma unroll
            for (int ni = 0; ni < 4; ni++) {
                const int mrow = kk * 16 + (lane & 15);
                uint32_t addr = bsb + (((s * 32 + mrow) * 36 + (wn >> 1) + ni * 4) << 2);
                uint32_t b0, b1;
                ldsm2t(b0, b1, addr);
                #pragma unroll
                for (int mi = 0; mi < 2; mi++)
                    mma_f16(acc[mi][ni], a[mi], b0, b1);
            }
        }
    }

    float* Sb = Sp + (size_t)z * EE * DD;
    #pragma unroll
    for (int mi = 0; mi < 2; mi++) {
        #pragma unroll
        for (int ni = 0; ni < 4; ni++) {
            const int e = e0 + wm + mi * 16 + (lane >> 2);
            const int d = d0 + wn + ni * 8 + 2 * (lane & 3);
            *(float2*)&Sb[(size_t)e * DD + d] =
                make_float2(acc[mi][ni][0], acc[mi][ni][1]);
            *(float2*)&Sb[(size_t)(e + 8) * DD + d] =
                make_float2(acc[mi][ni][2], acc[mi][ni][3]);
        }
    }
}

// Reduce 4 split-K partials ordered [b][sp]: S[b] = sum_sp Sp[b*4+sp]
__global__ __launch_bounds__(256) void reduce4(
    const float4* __restrict__ Sp, float4* __restrict__ S)
{
    const size_t per = (size_t)EE * DD / 4;
    size_t i = (size_t)blockIdx.x * 256 + threadIdx.x;
    if (i >= (size_t)BB * per) return;
    size_t b = i / per, j = i - b * per;
    const float4* p = Sp + 4 * b * per + j;
    float4 a = p[0], x = p[per], y = p[2 * per], w = p[3 * per];
    float4 r;
    r.x = (a.x + x.x) + (y.x + w.x);
    r.y = (a.y + x.y) + (y.y + w.y);
    r.z = (a.z + x.z) + (y.z + w.z);
    r.w = (a.w + x.w) + (y.w + w.w);
    S[i] = r;
}

// ---------------------------------------------------------------------------
// Flash attention, fp16 in/out, base-2 online softmax via bare MUFU.EX2
// (Q pre-scaled by 1/sqrt(dh)*log2e in the QKV epilogue).
// 128 q-rows per block, 256 threads / 8 warps. (R10 structure.)
// ---------------------------------------------------------------------------
__global__ __launch_bounds__(256) void flash_h(
    const __half* __restrict__ qkv, __half* __restrict__ o)
{
    __shared__ uint32_t Ks[2][64][20];
    __shared__ uint32_t Vs[2][64][20];
    __shared__ uint32_t Ps[128 * 36];

    const int bh = blockIdx.y;
    const int b = bh >> 3, h = bh & 7;
    const int m0 = blockIdx.x * 128;
    const int tid = threadIdx.x;
    const int lane = tid & 31;
    const int w16 = (tid >> 5) * 16;

    const size_t base = (size_t)(b * MM) * TD + h * DH;

    // ---- stage Q (already scaled fp16) into Ps scratch (pitch 20 u32) ----
    {
        const int r = tid >> 1;
        const __half* qp = &qkv[base + (size_t)(m0 + r) * TD + (tid & 1) * 16];
        uint32_t* d = &Ps[r * 20 + (tid & 1) * 8];
        *(uint4*)d       = *(const uint4*)qp;
        *(uint4*)(d + 4) = *(const uint4*)(qp + 8);
    }
    __syncthreads();
    uint32_t qa[2][4];
    #pragma unroll
    for (int kk = 0; kk < 2; kk++) {
        const int r = w16 + (lane >> 2), c = kk * 8 + (lane & 3);
        qa[kk][0] = Ps[r * 20 + c];        qa[kk][1] = Ps[(r + 8) * 20 + c];
        qa[kk][2] = Ps[r * 20 + c + 4];    qa[kk][3] = Ps[(r + 8) * 20 + c + 4];
    }
    __syncthreads();

    const uint32_t vsb = smem_u32(Vs);

    float O[4][4] = {};
    float mr0 = -1e30f, mr1 = -1e30f, l0 = 0.0f, l1 = 0.0f;

    const int rk = tid >> 2, ck = (tid & 3) * 8;
    uint4 ku, vu;
    {
        const __half* kp = &qkv[base + (size_t)rk * TD + 256 + ck];
        ku = *(const uint4*)kp;
        vu = *(const uint4*)(kp + 256);
    }

    const int ntile = MM / 64;
    for (int t = 0; t < ntile; t++) {
        const int s = t & 1;
        *(uint4*)&Ks[s][rk][(tid & 3) * 4] = ku;
        *(uint4*)&Vs[s][rk][(tid & 3) * 4] = vu;
        if (t + 1 < ntile) {
            const __half* kp = &qkv[base + (size_t)((t + 1) * 64 + rk) * TD + 256 + ck];
            ku = *(const uint4*)kp;
            vu = *(const uint4*)(kp + 256);
        }
        __syncthreads();

        // ---- S = Q @ K^T ----
        float sa[8][4] = {};
        #pragma unroll
        for (int j = 0; j < 8; j++) {
            #pragma unroll
            for (int kk = 0; kk < 2; kk++) {
                const int c = kk * 8 + (lane & 3);
                uint32_t b0 = Ks[s][j * 8 + (lane >> 2)][c];
                uint32_t b1 = Ks[s][j * 8 + (lane >> 2)][c + 4];
                mma_f16(sa[j], qa[kk], b0, b1);
            }
        }

        // ---- online softmax (base 2, bare MUFU.EX2) ----
        float mx0 = -1e30f, mx1 = -1e30f;
        #pragma unroll
        for (int j = 0; j < 8; j++) {
            mx0 = fmaxf(mx0, fmaxf(sa[j][0], sa[j][1]));
            mx1 = fmaxf(mx1, fmaxf(sa[j][2], sa[j][3]));
        }
        mx0 = fmaxf(mx0, __shfl_xor_sync(0xFFFFFFFFu, mx0, 1));
        mx0 = fmaxf(mx0, __shfl_xor_sync(0xFFFFFFFFu, mx0, 2));
        mx1 = fmaxf(mx1, __shfl_xor_sync(0xFFFFFFFFu, mx1, 1));
        mx1 = fmaxf(mx1, __shfl_xor_sync(0xFFFFFFFFu, mx1, 2));

        float mn0 = fmaxf(mr0, mx0), mn1 = fmaxf(mr1, mx1);
        float al0 = ex2(mr0 - mn0), al1 = ex2(mr1 - mn1);
        mr0 = mn0; mr1 = mn1;

        float s0 = 0.0f, s1 = 0.0f;
        const int pr = w16 + (lane >> 2);
        #pragma unroll
        for (int j = 0; j < 8; j++) {
            float p00 = ex2(sa[j][0] - mn0);
            float p01 = ex2(sa[j][1] - mn0);
            float p10 = ex2(sa[j][2] - mn1);
            float p11 = ex2(sa[j][3] - mn1);
            s0 += p00 + p01; s1 += p10 + p11;
            const int pc = j * 4 + (lane & 3);
            Ps[pr * 36 + pc]       = f2h2(p00, p01);
            Ps[(pr + 8) * 36 + pc] = f2h2(p10, p11);
        }
        s0 += __shfl_xor_sync(0xFFFFFFFFu, s0, 1);
        s0 += __shfl_xor_sync(0xFFFFFFFFu, s0, 2);
        s1 += __shfl_xor_sync(0xFFFFFFFFu, s1, 1);
        s1 += __shfl_xor_sync(0xFFFFFFFFu, s1, 2);
        l0 = l0 * al0 + s0;
        l1 = l1 * al1 + s1;
        #pragma unroll
        for (int ni = 0; ni < 4; ni++) {
            O[ni][0] *= al0; O[ni][1] *= al0;
            O[ni][2] *= al1; O[ni][3] *= al1;
        }
        __syncwarp();

        // ---- O += P @ V ----
        #pragma unroll
        for (int kc = 0; kc < 4; kc++) {
            uint32_t pa[4];
            const int c = kc * 8 + (lane & 3);
            pa[0] = Ps[pr * 36 + c];       pa[1] = Ps[(pr + 8) * 36 + c];
            pa[2] = Ps[pr * 36 + c + 4];   pa[3] = Ps[(pr + 8) * 36 + c + 4];
            const int vrow = kc * 16 + (lane & 15);
            #pragma unroll
            for (int ni = 0; ni < 4; ni++) {
                uint32_t addr = vsb + ((s * 64 + vrow) * 20 + ni * 4) * 4;
                uint32_t b0, b1;
                ldsm2t(b0, b1, addr);
                mma_f16(O[ni], pa, b0, b1);
            }
        }
    }

    const float inv0 = 1.0f / l0, inv1 = 1.0f / l1;
    #pragma unroll
    for (int ni = 0; ni < 4; ni++) {
        const int row = m0 + w16 + (lane >> 2);
        const int col = h * DH + ni * 8 + 2 * (lane & 3);
        size_t off = ((size_t)(b * MM) + row) * DD + col;
        *(__half2*)&o[off] = __floats2half2_rn(O[ni][0] * inv0, O[ni][1] * inv0);
        *(__half2*)&o[off + 8 * DD] =
            __floats2half2_rn(O[ni][2] * inv1, O[ni][3] * inv1);
    }
}

// ---------------------------------------------------------------------------
// Column softmax over e + multiply:  ef = half(S * softmax_e(S))
// ---------------------------------------------------------------------------
__global__ __launch_bounds__(256) void col_softmax_mul(
    const float* __restrict__ S, __half* __restrict__ ef)
{
    const int b  = blockIdx.y;
    const int d0 = blockIdx.x * 64;
    const int dx = threadIdx.x & 63, ry = threadIdx.x >> 6;
    const float* Sb = S  + (size_t)b * EE * DD + d0 + dx;
    __half*      Eb = ef + (size_t)b * EE * DD + d0 + dx;

    __shared__ float red[4][64];

    float m = -1e30f;
    for (int e = ry; e < EE; e += 4) m = fmaxf(m, Sb[(size_t)e * DD]);
    red[ry][dx] = m;
    __syncthreads();
    m = fmaxf(fmaxf(red[0][dx], red[1][dx]), fmaxf(red[2][dx], red[3][dx]));
    __syncthreads();

    float s = 0.0f;
    for (int e = ry; e < EE; e += 4) s += __expf(Sb[(size_t)e * DD] - m);
    red[ry][dx] = s;
    __syncthreads();
    s = red[0][dx] + red[1][dx] + red[2][dx] + red[3][dx];
    float inv = 1.0f / s;

    for (int e = ry; e < EE; e += 4) {
        float v = Sb[(size_t)e * DD];
        Eb[(size_t)e * DD] = __float2half(v * __expf(v - m) * inv);
    }
}

// ---------------------------------------------------------------------------
// LayerNorm (dim 256) + residual mix:  out = (1+alpha)*prev + (1-alpha)*LN(x)
// ---------------------------------------------------------------------------
__global__ __launch_bounds__(256) void ln_res(
    const float* __restrict__ ef2, const float* __restrict__ prev,
    const float* __restrict__ gamma, const float* __restrict__ beta,
    const float* __restrict__ alphap, float* __restrict__ out)
{
    const int row = blockIdx.x;
    const int c = threadIdx.x;
    const size_t off = (size_t)row * DD + c;

    float x = ef2[off];
    float s = x, q = x * x;
    #pragma unroll
    for (int o2 = 16; o2 > 0; o2 >>= 1) {
        s += __shfl_down_sync(0xFFFFFFFFu, s, o2);
        q += __shfl_down_sync(0xFFFFFFFFu, q, o2);
    }
    __shared__ float rs[8], rq[8], mv[2];
    int w = c >> 5, l = c & 31;
    if (l == 0) { rs[w] = s; rq[w] = q; }
    __syncthreads();
    if (c == 0) {
        float S2 = 0.0f, Q2 = 0.0f;
        #pragma unroll
        for (int i = 0; i < 8; i++) { S2 += rs[i]; Q2 += rq[i]; }
        float mean = S2 * (1.0f / 256.0f);
        float var  = Q2 * (1.0f / 256.0f) - mean * mean;
        mv[0] = mean;
        mv[1] = rsqrtf(var + 1e-5f);
    }
    __syncthreads();

    float n = (x - mv[0]) * mv[1] * gamma[c] + beta[c];
    float a = *alphap;
    float p = prev[off];
    out[off] = (1.0f + a) * p + (1.0f - a) * n;
}

// ---------------------------------------------------------------------------
// Launch
// ---------------------------------------------------------------------------
extern "C" void kernel_launch(void* const* d_in, const int* in_sizes, int n_in,
                              void* d_out, int out_size)
{
    const float* feat = (const float*)d_in[0];
    const float* inc  = (const float*)d_in[1];
    const float* prev = (const float*)d_in[2];
    const float* ipw  = (const float*)d_in[3];
    const float* ipb  = (const float*)d_in[4];
    const float* opw  = (const float*)d_in[5];
    const float* opb  = (const float*)d_in[6];
    const float* pw   = (const float*)d_in[7];
    const float* gam  = (const float*)d_in[8];
    const float* bet  = (const float*)d_in[9];
    const float* alp  = (const float*)d_in[10];
    float* out = (float*)d_out;

    __half *qkvh, *attnh, *attnph, *efh;
    float *Sp, *Sb, *ef2;
    cudaGetSymbolAddress((void**)&qkvh,   g_qkvh);
    cudaGetSymbolAddress((void**)&attnh,  g_attnh);
    cudaGetSymbolAddress((void**)&attnph, g_attnph);
    cudaGetSymbolAddress((void**)&Sp,     g_Sp);
    cudaGetSymbolAddress((void**)&Sb,     g_S);
    cudaGetSymbolAddress((void**)&efh,    g_efh);
    cudaGetSymbolAddress((void**)&ef2,    g_ef2);

    // 1/sqrt(32) * log2(e): base-2 softmax absorbed into Q scaling
    const float qscale = 0.17677669529663689f * 1.4426950408889634f;

    // 1. QKV projection -> fp16, Q third pre-scaled
    hgemm_nt<128, float, __half>
        <<<dim3(TD / 128, (BB * MM) / 128), 256>>>(
            feat, ipw, ipb, qkvh, DD, DD, TD, DD, qscale);

    // 2. flash attention (fp16 in/out, base-2 softmax)
    flash_h<<<dim3(MM / 128, BB * HH), 256>>>(qkvh, attnh);

    // 3. out projection -> fp16 attnph
    hgemm_nt<64, __half, __half>
        <<<dim3(DD / 64, (BB * MM) / 128), 256>>>(
            attnh, opw, opb, attnph, DD, DD, DD, 0, 1.0f);

    // 4. S = inc^T @ attnph  (TN fp16, split-K x4) + reduce
    sgemm_tn_h<<<dim3(DD / 64, EE / 128, BB * 4), 256>>>(inc, attnph, Sp);
    reduce4<<<(BB * EE * DD / 4 + 255) / 256, 256>>>((const float4*)Sp,
                                                     (float4*)Sb);

    // 5. ef = half(S * softmax_e(S))
    col_softmax_mul<<<dim3(DD / 64, BB), 256>>>(Sb, efh);

    // 6. ef2 = ef @ proj_w^T
    hgemm_nt<64, __half, float>
        <<<dim3(DD / 64, (BB * EE) / 128), 256>>>(
            efh, pw, nullptr, ef2, DD, DD, DD, 0, 1.0f);

    // 7. LayerNorm + residual mix
    ln_res<<<BB * EE, 256>>>(ef2, prev, gam, bet, alp, out);
}

// round 14
// speedup vs baseline: 1.5367x; 1.5149x over previous
#include <cuda_runtime.h>
#include <cuda_fp16.h>
#include <math.h>
#include <stdint.h>

// Problem constants
#define BB   4
#define MM   2048
#define DD   256
#define EE   1024
#define HH   8
#define DH   32
#define TD   768   // 3*DD

// ---------------------------------------------------------------------------
// Scratch (no cudaMalloc allowed)
// ---------------------------------------------------------------------------
__device__ __half g_qkvh  [BB * MM * TD];      // 12 MB (Q pre-scaled by 1/sqrt(dh)*log2e)
__device__ __half g_attnh [BB * MM * DD];      // 4 MB
__device__ __half g_attnph[BB * MM * DD];      // 4 MB
__device__ __half g_inch  [BB * MM * EE];      // 16 MB (inc as fp16)
__device__ float  g_Sp    [4 * BB * EE * DD];  // 16 MB (split-K partials)
__device__ float  g_S     [BB * EE * DD];      // 4 MB
__device__ __half g_efh   [BB * EE * DD];      // 2 MB
__device__ float  g_ef2   [BB * EE * DD];      // 4 MB

// ---------------------------------------------------------------------------
// Helpers
// ---------------------------------------------------------------------------
__device__ __forceinline__ uint32_t f2h2(float a, float b) {
    __half2 h = __floats2half2_rn(a, b);
    return *reinterpret_cast<uint32_t*>(&h);
}

// bare MUFU.EX2 — guaranteed single-instruction exp2
__device__ __forceinline__ float ex2(float x) {
    float r;
    asm("ex2.approx.f32 %0, %1;" : "=f"(r) : "f"(x));
    return r;
}

__device__ __forceinline__ void mma_f16(float* c, const uint32_t* a,
                                        uint32_t b0, uint32_t b1) {
    asm volatile(
        "mma.sync.aligned.m16n8k16.row.col.f32.f16.f16.f32 "
        "{%0,%1,%2,%3}, {%4,%5,%6,%7}, {%8,%9}, {%0,%1,%2,%3};\n"
        : "+f"(c[0]), "+f"(c[1]), "+f"(c[2]), "+f"(c[3])
        : "r"(a[0]), "r"(a[1]), "r"(a[2]), "r"(a[3]), "r"(b0), "r"(b1));
}

__device__ __forceinline__ void ldsm2t(uint32_t& b0, uint32_t& b1,
                                       uint32_t addr) {
    asm volatile("ldmatrix.sync.aligned.m8n8.x2.trans.shared.b16 {%0,%1}, [%2];"
                 : "=r"(b0), "=r"(b1) : "r"(addr));
}

__device__ __forceinline__ void ldsm4t(uint32_t* a, uint32_t addr) {
    asm volatile("ldmatrix.sync.aligned.m8n8.x4.trans.shared.b16 {%0,%1,%2,%3}, [%4];"
                 : "=r"(a[0]), "=r"(a[1]), "=r"(a[2]), "=r"(a[3]) : "r"(addr));
}

__device__ __forceinline__ uint32_t smem_u32(const void* p) {
    uint32_t a;
    asm("{ .reg .u64 t; cvta.to.shared.u64 t, %1; cvt.u32.u64 %0, t; }"
        : "=r"(a) : "l"(p));
    return a;
}

// ---------------------------------------------------------------------------
// fp32 -> fp16 bulk convert (for inc): 8 elements per thread
// ---------------------------------------------------------------------------
__global__ __launch_bounds__(256) void f2h_bulk(
    const float4* __restrict__ in, uint4* __restrict__ out, int n8)
{
    int i = blockIdx.x * 256 + threadIdx.x;
    if (i >= n8) return;
    float4 a = in[2 * i], b = in[2 * i + 1];
    uint4 r;
    r.x = f2h2(a.x, a.y); r.y = f2h2(a.z, a.w);
    r.z = f2h2(b.x, b.y); r.w = f2h2(b.z, b.w);
    out[i] = r;
}

// ---------------------------------------------------------------------------
// fp16 NT GEMM: C[M,N] = A[M,K] @ B[N,K]^T (+bias), fp32 accumulate.
// BM=128, BK=32, BN template. 256 threads, 8 warps (4m x 2n).
// Columns c < scale_cols get multiplied by qs after bias (Q pre-scaling).
// ---------------------------------------------------------------------------
template <int BN, typename TA, typename TC>
__global__ __launch_bounds__(256) void hgemm_nt(
    const TA* __restrict__ A, const float* __restrict__ W,
    const float* __restrict__ bias, TC* __restrict__ C,
    int K, int lda, int ldc, int scale_cols, float qs)
{
    constexpr int NF = BN / 16;
    __shared__ uint32_t As[2][128][20];
    __shared__ uint32_t Bs[2][BN][20];

    const int tid = threadIdx.x, lane = tid & 31, wid = tid >> 5;
    const int wm = (wid >> 1) * 32, wn = (wid & 1) * (BN / 2);
    const int m0 = blockIdx.y * 128, n0 = blockIdx.x * BN;

    const int ar = tid >> 1;
    constexpr int TPB = 256 / BN;
    constexpr int BH  = 32 / TPB;
    const int br = tid / TPB;

    const TA* Ap = A + (size_t)(m0 + ar) * lda + (tid & 1) * 16;
    const float* Wp = W + (size_t)(n0 + br) * K + (tid % TPB) * BH;

    float4 paf[4], pbf[BH / 4];
    uint4  pah[2];

    auto loadA = [&](int k0) {
        if constexpr (sizeof(TA) == 4) {
            const float* p = (const float*)Ap + k0;
            #pragma unroll
            for (int i = 0; i < 4; i++) paf[i] = *(const float4*)(p + i * 4);
        } else {
            const __half* p = (const __half*)Ap + k0;
            pah[0] = *(const uint4*)p;
            pah[1] = *(const uint4*)(p + 8);
        }
    };
    auto storeA = [&](int s) {
        uint32_t* d = &As[s][ar][(tid & 1) * 8];
        if constexpr (sizeof(TA) == 4) {
            #pragma unroll
            for (int i = 0; i < 4; i++) {
                d[2 * i]     = f2h2(paf[i].x, paf[i].y);
                d[2 * i + 1] = f2h2(paf[i].z, paf[i].w);
            }
        } else {
            *(uint4*)d = pah[0];
            *(uint4*)(d + 4) = pah[1];
        }
    };
    auto loadB = [&](int k0) {
        const float* p = Wp + k0;
        #pragma unroll
        for (int i = 0; i < BH / 4; i++) pbf[i] = *(const float4*)(p + i * 4);
    };
    auto storeB = [&](int s) {
        uint32_t* d = &Bs[s][br][(tid % TPB) * (BH / 2)];
        #pragma unroll
        for (int i = 0; i < BH / 4; i++) {
            d[2 * i]     = f2h2(pbf[i].x, pbf[i].y);
            d[2 * i + 1] = f2h2(pbf[i].z, pbf[i].w);
        }
    };

    float acc[2][NF][4] = {};
    loadA(0); loadB(0);

    const int nk = K >> 5;
    for (int t = 0; t < nk; t++) {
        const int s = t & 1;
        storeA(s); storeB(s);
        if (t + 1 < nk) { loadA((t + 1) * 32); loadB((t + 1) * 32); }
        __syncthreads();

        #pragma unroll
        for (int kk = 0; kk < 2; kk++) {
            uint32_t a[2][4];
            const int c = kk * 8 + (lane & 3);
            #pragma unroll
            for (int mi = 0; mi < 2; mi++) {
                const int r = wm + mi * 16 + (lane >> 2);
                a[mi][0] = As[s][r][c];     a[mi][1] = As[s][r + 8][c];
                a[mi][2] = As[s][r][c + 4]; a[mi][3] = As[s][r + 8][c + 4];
            }
            #pragma unroll
            for (int ni = 0; ni < NF; ni++) {
                const int n = wn + ni * 8 + (lane >> 2);
                uint32_t b0 = Bs[s][n][c], b1 = Bs[s][n][c + 4];
                #pragma unroll
                for (int mi = 0; mi < 2; mi++)
                    mma_f16(acc[mi][ni], a[mi], b0, b1);
            }
        }
    }

    #pragma unroll
    for (int mi = 0; mi < 2; mi++) {
        #pragma unroll
        for (int ni = 0; ni < NF; ni++) {
            const int r = m0 + wm + mi * 16 + (lane >> 2);
            const int c = n0 + wn + ni * 8 + 2 * (lane & 3);
            float b0 = bias ? bias[c] : 0.0f;
            float b1 = bias ? bias[c + 1] : 0.0f;
            float v0 = acc[mi][ni][0] + b0, v1 = acc[mi][ni][1] + b1;
            float v2 = acc[mi][ni][2] + b0, v3 = acc[mi][ni][3] + b1;
            if (c < scale_cols) { v0 *= qs; v1 *= qs; v2 *= qs; v3 *= qs; }
            if constexpr (sizeof(TC) == 2) {
                *(__half2*)&C[(size_t)r * ldc + c]       = __floats2half2_rn(v0, v1);
                *(__half2*)&C[(size_t)(r + 8) * ldc + c] = __floats2half2_rn(v2, v3);
            } else {
                *(float2*)&C[(size_t)r * ldc + c]       = make_float2(v0, v1);
                *(float2*)&C[(size_t)(r + 8) * ldc + c] = make_float2(v2, v3);
            }
        }
    }
}

// ---------------------------------------------------------------------------
// fp16 TN GEMM (for S): Sp[z][e][d] = sum_m inch[b][m][e] * attnph[b][m][d]
// Both operands fp16, m-major; pure uint4 staging; ldmatrix.trans fragments.
// BM=128(e), BN=64(d), BK=32(m), 256 threads, min 3 CTAs/SM.
// Split-K x4 over m (512 each): z = blockIdx.z, bz=z>>2, sp=z&3.
// ---------------------------------------------------------------------------
__global__ __launch_bounds__(256, 3) void sgemm_tn_h(
    const __half* __restrict__ inch, const __half* __restrict__ Bh,
    float* __restrict__ Sp)
{
    __shared__ uint32_t As[2][32][68];   // [m][e-pairs]
    __shared__ uint32_t Bs[2][32][36];   // [m][d-pairs]

    const int tid = threadIdx.x, lane = tid & 31, wid = tid >> 5;
    const int wm = (wid >> 1) * 32, wn = (wid & 1) * 32;
    const int z = blockIdx.z, bz = z >> 2, sp = z & 3;
    const int e0 = blockIdx.y * 128, d0 = blockIdx.x * 64;
    const __half* Ab = inch + (size_t)bz * MM * EE + (size_t)(sp * 512) * EE;
    const __half* Bb = Bh   + (size_t)bz * MM * DD + (size_t)(sp * 512) * DD;

    const int am = tid >> 3;
    const __half* Apt = Ab + (size_t)am * EE + e0 + (tid & 7) * 16;
    const __half* Bpt = Bb + (size_t)am * DD + d0 + (tid & 7) * 8;

    uint4 pa0, pa1, pb;
    auto loadT = [&](int k0) {
        const __half* p = Apt + (size_t)k0 * EE;
        pa0 = *(const uint4*)p;
        pa1 = *(const uint4*)(p + 8);
        pb  = *(const uint4*)(Bpt + (size_t)k0 * DD);
    };
    auto storeT = [&](int s) {
        uint32_t* da = &As[s][am][(tid & 7) * 8];
        *(uint4*)da       = pa0;
        *(uint4*)(da + 4) = pa1;
        *(uint4*)&Bs[s][am][(tid & 7) * 4] = pb;
    };

    const uint32_t asb = smem_u32(As), bsb = smem_u32(Bs);

    float acc[2][4][4] = {};
    loadT(0);

    for (int t = 0; t < 16; t++) {   // 512 / 32
        const int s = t & 1;
        storeT(s);
        if (t + 1 < 16) loadT((t + 1) * 32);
        __syncthreads();

        #pragma unroll
        for (int kk = 0; kk < 2; kk++) {
            uint32_t a[2][4];
            #pragma unroll
            for (int mi = 0; mi < 2; mi++) {
                const int mrow = kk * 16 + (lane & 7) + ((lane & 16) >> 1);
                const int ecol = wm + mi * 16 + (lane & 8);
                uint32_t addr = asb + (((s * 32 + mrow) * 68 + (ecol >> 1)) << 2);
                ldsm4t(a[mi], addr);
            }
            #pragma unroll
            for (int ni = 0; ni < 4; ni++) {
                const int mrow = kk * 16 + (lane & 15);
                uint32_t addr = bsb + (((s * 32 + mrow) * 36 + (wn >> 1) + ni * 4) << 2);
                uint32_t b0, b1;
                ldsm2t(b0, b1, addr);
                #pragma unroll
                for (int mi = 0; mi < 2; mi++)
                    mma_f16(acc[mi][ni], a[mi], b0, b1);
            }
        }
    }

    float* Sb = Sp + (size_t)z * EE * DD;
    #pragma unroll
    for (int mi = 0; mi < 2; mi++) {
        #pragma unroll
        for (int ni = 0; ni < 4; ni++) {
            const int e = e0 + wm + mi * 16 + (lane >> 2);
            const int d = d0 + wn + ni * 8 + 2 * (lane & 3);
            *(float2*)&Sb[(size_t)e * DD + d] =
                make_float2(acc[mi][ni][0], acc[mi][ni][1]);
            *(float2*)&Sb[(size_t)(e + 8) * DD + d] =
                make_float2(acc[mi][ni][2], acc[mi][ni][3]);
        }
    }
}

// Reduce 4 split-K partials ordered [b][sp]: S[b] = sum_sp Sp[b*4+sp]
__global__ __launch_bounds__(256) void reduce4(
    const float4* __restrict__ Sp, float4* __restrict__ S)
{
    const size_t per = (size_t)EE * DD / 4;
    size_t i = (size_t)blockIdx.x * 256 + threadIdx.x;
    if (i >= (size_t)BB * per) return;
    size_t b = i / per, j = i - b * per;
    const float4* p = Sp + 4 * b * per + j;
    float4 a = p[0], x = p[per], y = p[2 * per], w = p[3 * per];
    float4 r;
    r.x = (a.x + x.x) + (y.x + w.x);
    r.y = (a.y + x.y) + (y.y + w.y);
    r.z = (a.z + x.z) + (y.z + w.z);
    r.w = (a.w + x.w) + (y.w + w.w);
    S[i] = r;
}

// ---------------------------------------------------------------------------
// Flash attention, fp16 in/out, base-2 online softmax via bare MUFU.EX2
// (Q pre-scaled by 1/sqrt(dh)*log2e in the QKV epilogue).
// 128 q-rows per block, 256 threads / 8 warps.
// ---------------------------------------------------------------------------
__global__ __launch_bounds__(256) void flash_h(
    const __half* __restrict__ qkv, __half* __restrict__ o)
{
    __shared__ uint32_t Ks[2][64][20];
    __shared__ uint32_t Vs[2][64][20];
    __shared__ uint32_t Ps[128 * 36];

    const int bh = blockIdx.y;
    const int b = bh >> 3, h = bh & 7;
    const int m0 = blockIdx.x * 128;
    const int tid = threadIdx.x;
    const int lane = tid & 31;
    const int w16 = (tid >> 5) * 16;

    const size_t base = (size_t)(b * MM) * TD + h * DH;

    // ---- stage Q (already scaled fp16) into Ps scratch (pitch 20 u32) ----
    {
        const int r = tid >> 1;
        const __half* qp = &qkv[base + (size_t)(m0 + r) * TD + (tid & 1) * 16];
        uint32_t* d = &Ps[r * 20 + (tid & 1) * 8];
        *(uint4*)d       = *(const uint4*)qp;
        *(uint4*)(d + 4) = *(const uint4*)(qp + 8);
    }
    __syncthreads();
    uint32_t qa[2][4];
    #pragma unroll
    for (int kk = 0; kk < 2; kk++) {
        const int r = w16 + (lane >> 2), c = kk * 8 + (lane & 3);
        qa[kk][0] = Ps[r * 20 + c];        qa[kk][1] = Ps[(r + 8) * 20 + c];
        qa[kk][2] = Ps[r * 20 + c + 4];    qa[kk][3] = Ps[(r + 8) * 20 + c + 4];
    }
    __syncthreads();

    const uint32_t vsb = smem_u32(Vs);

    float O[4][4] = {};
    float mr0 = -1e30f, mr1 = -1e30f, l0 = 0.0f, l1 = 0.0f;

    const int rk = tid >> 2, ck = (tid & 3) * 8;
    uint4 ku, vu;
    {
        const __half* kp = &qkv[base + (size_t)rk * TD + 256 + ck];
        ku = *(const uint4*)kp;
        vu = *(const uint4*)(kp + 256);
    }

    const int ntile = MM / 64;
    for (int t = 0; t < ntile; t++) {
        const int s = t & 1;
        *(uint4*)&Ks[s][rk][(tid & 3) * 4] = ku;
        *(uint4*)&Vs[s][rk][(tid & 3) * 4] = vu;
        if (t + 1 < ntile) {
            const __half* kp = &qkv[base + (size_t)((t + 1) * 64 + rk) * TD + 256 + ck];
            ku = *(const uint4*)kp;
            vu = *(const uint4*)(kp + 256);
        }
        __syncthreads();

        // ---- S = Q @ K^T ----
        float sa[8][4] = {};
        #pragma unroll
        for (int j = 0; j < 8; j++) {
            #pragma unroll
            for (int kk = 0; kk < 2; kk++) {
                const int c = kk * 8 + (lane & 3);
                uint32_t b0 = Ks[s][j * 8 + (lane >> 2)][c];
                uint32_t b1 = Ks[s][j * 8 + (lane >> 2)][c + 4];
                mma_f16(sa[j], qa[kk], b0, b1);
            }
        }

        // ---- online softmax (base 2, bare MUFU.EX2) ----
        float mx0 = -1e30f, mx1 = -1e30f;
        #pragma unroll
        for (int j = 0; j < 8; j++) {
            mx0 = fmaxf(mx0, fmaxf(sa[j][0], sa[j][1]));
            mx1 = fmaxf(mx1, fmaxf(sa[j][2], sa[j][3]));
        }
        mx0 = fmaxf(mx0, __shfl_xor_sync(0xFFFFFFFFu, mx0, 1));
        mx0 = fmaxf(mx0, __shfl_xor_sync(0xFFFFFFFFu, mx0, 2));
        mx1 = fmaxf(mx1, __shfl_xor_sync(0xFFFFFFFFu, mx1, 1));
        mx1 = fmaxf(mx1, __shfl_xor_sync(0xFFFFFFFFu, mx1, 2));

        float mn0 = fmaxf(mr0, mx0), mn1 = fmaxf(mr1, mx1);
        float al0 = ex2(mr0 - mn0), al1 = ex2(mr1 - mn1);
        mr0 = mn0; mr1 = mn1;

        float s0 = 0.0f, s1 = 0.0f;
        const int pr = w16 + (lane >> 2);
        #pragma unroll
        for (int j = 0; j < 8; j++) {
            float p00 = ex2(sa[j][0] - mn0);
            float p01 = ex2(sa[j][1] - mn0);
            float p10 = ex2(sa[j][2] - mn1);
            float p11 = ex2(sa[j][3] - mn1);
            s0 += p00 + p01; s1 += p10 + p11;
            const int pc = j * 4 + (lane & 3);
            Ps[pr * 36 + pc]       = f2h2(p00, p01);
            Ps[(pr + 8) * 36 + pc] = f2h2(p10, p11);
        }
        s0 += __shfl_xor_sync(0xFFFFFFFFu, s0, 1);
        s0 += __shfl_xor_sync(0xFFFFFFFFu, s0, 2);
        s1 += __shfl_xor_sync(0xFFFFFFFFu, s1, 1);
        s1 += __shfl_xor_sync(0xFFFFFFFFu, s1, 2);
        l0 = l0 * al0 + s0;
        l1 = l1 * al1 + s1;
        #pragma unroll
        for (int ni = 0; ni < 4; ni++) {
            O[ni][0] *= al0; O[ni][1] *= al0;
            O[ni][2] *= al1; O[ni][3] *= al1;
        }
        __syncwarp();

        // ---- O += P @ V ----
        #pragma unroll
        for (int kc = 0; kc < 4; kc++) {
            uint32_t pa[4];
            const int c = kc * 8 + (lane & 3);
            pa[0] = Ps[pr * 36 + c];       pa[1] = Ps[(pr + 8) * 36 + c];
            pa[2] = Ps[pr * 36 + c + 4];   pa[3] = Ps[(pr + 8) * 36 + c + 4];
            const int vrow = kc * 16 + (lane & 15);
            #pragma unroll
            for (int ni = 0; ni < 4; ni++) {
                uint32_t addr = vsb + ((s * 64 + vrow) * 20 + ni * 4) * 4;
                uint32_t b0, b1;
                ldsm2t(b0, b1, addr);
                mma_f16(O[ni], pa, b0, b1);
            }
        }
    }

    const float inv0 = 1.0f / l0, inv1 = 1.0f / l1;
    #pragma unroll
    for (int ni = 0; ni < 4; ni++) {
        const int row = m0 + w16 + (lane >> 2);
        const int col = h * DH + ni * 8 + 2 * (lane & 3);
        size_t off = ((size_t)(b * MM) + row) * DD + col;
        *(__half2*)&o[off] = __floats2half2_rn(O[ni][0] * inv0, O[ni][1] * inv0);
        *(__half2*)&o[off + 8 * DD] =
            __floats2half2_rn(O[ni][2] * inv1, O[ni][3] * inv1);
    }
}

// ---------------------------------------------------------------------------
// Column softmax over e + multiply:  ef = half(S * softmax_e(S))
// ---------------------------------------------------------------------------
__global__ __launch_bounds__(256) void col_softmax_mul(
    const float* __restrict__ S, __half* __restrict__ ef)
{
    const int b  = blockIdx.y;
    const int d0 = blockIdx.x * 64;
    const int dx = threadIdx.x & 63, ry = threadIdx.x >> 6;
    const float* Sb = S  + (size_t)b * EE * DD + d0 + dx;
    __half*      Eb = ef + (size_t)b * EE * DD + d0 + dx;

    __shared__ float red[4][64];

    float m = -1e30f;
    for (int e = ry; e < EE; e += 4) m = fmaxf(m, Sb[(size_t)e * DD]);
    red[ry][dx] = m;
    __syncthreads();
    m = fmaxf(fmaxf(red[0][dx], red[1][dx]), fmaxf(red[2][dx], red[3][dx]));
    __syncthreads();

    float s = 0.0f;
    for (int e = ry; e < EE; e += 4) s += __expf(Sb[(size_t)e * DD] - m);
    red[ry][dx] = s;
    __syncthreads();
    s = red[0][dx] + red[1][dx] + red[2][dx] + red[3][dx];
    float inv = 1.0f / s;

    for (int e = ry; e < EE; e += 4) {
        float v = Sb[(size_t)e * DD];
        Eb[(size_t)e * DD] = __float2half(v * __expf(v - m) * inv);
    }
}

// ---------------------------------------------------------------------------
// LayerNorm (dim 256) + residual mix:  out = (1+alpha)*prev + (1-alpha)*LN(x)
// ---------------------------------------------------------------------------
__global__ __launch_bounds__(256) void ln_res(
    const float* __restrict__ ef2, const float* __restrict__ prev,
    const float* __restrict__ gamma, const float* __restrict__ beta,
    const float* __restrict__ alphap, float* __restrict__ out)
{
    const int row = blockIdx.x;
    const int c = threadIdx.x;
    const size_t off = (size_t)row * DD + c;

    float x = ef2[off];
    float s = x, q = x * x;
    #pragma unroll
    for (int o2 = 16; o2 > 0; o2 >>= 1) {
        s += __shfl_down_sync(0xFFFFFFFFu, s, o2);
        q += __shfl_down_sync(0xFFFFFFFFu, q, o2);
    }
    __shared__ float rs[8], rq[8], mv[2];
    int w = c >> 5, l = c & 31;
    if (l == 0) { rs[w] = s; rq[w] = q; }
    __syncthreads();
    if (c == 0) {
        float S2 = 0.0f, Q2 = 0.0f;
        #pragma unroll
        for (int i = 0; i < 8; i++) { S2 += rs[i]; Q2 += rq[i]; }
        float mean = S2 * (1.0f / 256.0f);
        float var  = Q2 * (1.0f / 256.0f) - mean * mean;
        mv[0] = mean;
        mv[1] = rsqrtf(var + 1e-5f);
    }
    __syncthreads();

    float n = (x - mv[0]) * mv[1] * gamma[c] + beta[c];
    float a = *alphap;
    float p = prev[off];
    out[off] = (1.0f + a) * p + (1.0f - a) * n;
}

// ---------------------------------------------------------------------------
// Launch
// ---------------------------------------------------------------------------
extern "C" void kernel_launch(void* const* d_in, const int* in_sizes, int n_in,
                              void* d_out, int out_size)
{
    const float* feat = (const float*)d_in[0];
    const float* inc  = (const float*)d_in[1];
    const float* prev = (const float*)d_in[2];
    const float* ipw  = (const float*)d_in[3];
    const float* ipb  = (const float*)d_in[4];
    const float* opw  = (const float*)d_in[5];
    const float* opb  = (const float*)d_in[6];
    const float* pw   = (const float*)d_in[7];
    const float* gam  = (const float*)d_in[8];
    const float* bet  = (const float*)d_in[9];
    const float* alp  = (const float*)d_in[10];
    float* out = (float*)d_out;

    __half *qkvh, *attnh, *attnph, *inch, *efh;
    float *Sp, *Sb, *ef2;
    cudaGetSymbolAddress((void**)&qkvh,   g_qkvh);
    cudaGetSymbolAddress((void**)&attnh,  g_attnh);
    cudaGetSymbolAddress((void**)&attnph, g_attnph);
    cudaGetSymbolAddress((void**)&inch,   g_inch);
    cudaGetSymbolAddress((void**)&Sp,     g_Sp);
    cudaGetSymbolAddress((void**)&Sb,     g_S);
    cudaGetSymbolAddress((void**)&efh,    g_efh);
    cudaGetSymbolAddress((void**)&ef2,    g_ef2);

    // 1/sqrt(32) * log2(e): base-2 softmax absorbed into Q scaling
    const float qscale = 0.17677669529663689f * 1.4426950408889634f;

    // 0. convert inc -> fp16 (8 elems/thread)
    {
        const int n8 = BB * MM * EE / 8;
        f2h_bulk<<<(n8 + 255) / 256, 256>>>((const float4*)inc,
                                            (uint4*)inch, n8);
    }

    // 1. QKV projection -> fp16, Q third pre-scaled
    hgemm_nt<128, float, __half>
        <<<dim3(TD / 128, (BB * MM) / 128), 256>>>(
            feat, ipw, ipb, qkvh, DD, DD, TD, DD, qscale);

    // 2. flash attention (fp16 in/out, base-2 softmax)
    flash_h<<<dim3(MM / 128, BB * HH), 256>>>(qkvh, attnh);

    // 3. out projection -> fp16 attnph
    hgemm_nt<64, __half, __half>
        <<<dim3(DD / 64, (BB * MM) / 128), 256>>>(
            attnh, opw, opb, attnph, DD, DD, DD, 0, 1.0f);

    // 4. S = inch^T @ attnph  (TN fp16, split-K x4) + reduce
    sgemm_tn_h<<<dim3(DD / 64, EE / 128, BB * 4), 256>>>(inch, attnph, Sp);
    reduce4<<<(BB * EE * DD / 4 + 255) / 256, 256>>>((const float4*)Sp,
                                                     (float4*)Sb);

    // 5. ef = half(S * softmax_e(S))
    col_softmax_mul<<<dim3(DD / 64, BB), 256>>>(Sb, efh);

    // 6. ef2 = ef @ proj_w^T
    hgemm_nt<64, __half, float>
        <<<dim3(DD / 64, (BB * EE) / 128), 256>>>(
            efh, pw, nullptr, ef2, DD, DD, DD, 0, 1.0f);

    // 7. LayerNorm + residual mix
    ln_res<<<BB * EE, 256>>>(ef2, prev, gam, bet, alp, out);
}

// round 16
// speedup vs baseline: 1.5814x; 1.0291x over previous
#include <cuda_runtime.h>
#include <cuda_fp16.h>
#include <math.h>
#include <stdint.h>

// Problem constants
#define BB   4
#define MM   2048
#define DD   256
#define EE   1024
#define HH   8
#define DH   32
#define TD   768   // 3*DD

// ---------------------------------------------------------------------------
// Scratch (no cudaMalloc allowed)
// ---------------------------------------------------------------------------
__device__ __half g_qkvh  [BB * MM * TD];      // 12 MB (Q pre-scaled by 1/sqrt(dh)*log2e)
__device__ __half g_attnh [BB * MM * DD];      // 4 MB
__device__ __half g_attnph[BB * MM * DD];      // 4 MB
__device__ __half g_inch  [BB * MM * EE];      // 16 MB (inc as fp16)
__device__ float  g_Sp    [4 * BB * EE * DD];  // 16 MB (split-K partials)
__device__ float  g_S     [BB * EE * DD];      // 4 MB
__device__ __half g_efh   [BB * EE * DD];      // 2 MB
__device__ float  g_ef2   [BB * EE * DD];      // 4 MB

// ---------------------------------------------------------------------------
// Helpers
// ---------------------------------------------------------------------------
__device__ __forceinline__ uint32_t f2h2(float a, float b) {
    __half2 h = __floats2half2_rn(a, b);
    return *reinterpret_cast<uint32_t*>(&h);
}

// bare MUFU.EX2 — guaranteed single-instruction exp2
__device__ __forceinline__ float ex2(float x) {
    float r;
    asm("ex2.approx.f32 %0, %1;" : "=f"(r) : "f"(x));
    return r;
}

__device__ __forceinline__ void mma_f16(float* c, const uint32_t* a,
                                        uint32_t b0, uint32_t b1) {
    asm volatile(
        "mma.sync.aligned.m16n8k16.row.col.f32.f16.f16.f32 "
        "{%0,%1,%2,%3}, {%4,%5,%6,%7}, {%8,%9}, {%0,%1,%2,%3};\n"
        : "+f"(c[0]), "+f"(c[1]), "+f"(c[2]), "+f"(c[3])
        : "r"(a[0]), "r"(a[1]), "r"(a[2]), "r"(a[3]), "r"(b0), "r"(b1));
}

__device__ __forceinline__ void ldsm2t(uint32_t& b0, uint32_t& b1,
                                       uint32_t addr) {
    asm volatile("ldmatrix.sync.aligned.m8n8.x2.trans.shared.b16 {%0,%1}, [%2];"
                 : "=r"(b0), "=r"(b1) : "r"(addr));
}

__device__ __forceinline__ void ldsm4t(uint32_t* a, uint32_t addr) {
    asm volatile("ldmatrix.sync.aligned.m8n8.x4.trans.shared.b16 {%0,%1,%2,%3}, [%4];"
                 : "=r"(a[0]), "=r"(a[1]), "=r"(a[2]), "=r"(a[3]) : "r"(addr));
}

__device__ __forceinline__ uint32_t smem_u32(const void* p) {
    uint32_t a;
    asm("{ .reg .u64 t; cvta.to.shared.u64 t, %1; cvt.u32.u64 %0, t; }"
        : "=r"(a) : "l"(p));
    return a;
}

__device__ __forceinline__ void cp16(uint32_t saddr, const void* g) {
    asm volatile("cp.async.cg.shared.global [%0], [%1], 16;"
                 :: "r"(saddr), "l"(g));
}
#define CP_COMMIT() asm volatile("cp.async.commit_group;" ::: "memory")
#define CP_WAIT1()  asm volatile("cp.async.wait_group 1;" ::: "memory")
#define CP_WAIT0()  asm volatile("cp.async.wait_group 0;" ::: "memory")

// ---------------------------------------------------------------------------
// fp32 -> fp16 bulk convert (for inc): 8 elements per thread
// ---------------------------------------------------------------------------
__global__ __launch_bounds__(256) void f2h_bulk(
    const float4* __restrict__ in, uint4* __restrict__ out, int n8)
{
    int i = blockIdx.x * 256 + threadIdx.x;
    if (i >= n8) return;
    float4 a = in[2 * i], b = in[2 * i + 1];
    uint4 r;
    r.x = f2h2(a.x, a.y); r.y = f2h2(a.z, a.w);
    r.z = f2h2(b.x, b.y); r.w = f2h2(b.z, b.w);
    out[i] = r;
}

// ---------------------------------------------------------------------------
// fp16 NT GEMM: C[M,N] = A[M,K] @ B[N,K]^T (+bias), fp32 accumulate.
// BM=128, BK=32, BN template. 256 threads, 8 warps (4m x 2n).  (R14 version)
// ---------------------------------------------------------------------------
template <int BN, typename TA, typename TC>
__global__ __launch_bounds__(256) void hgemm_nt(
    const TA* __restrict__ A, const float* __restrict__ W,
    const float* __restrict__ bias, TC* __restrict__ C,
    int K, int lda, int ldc, int scale_cols, float qs)
{
    constexpr int NF = BN / 16;
    __shared__ uint32_t As[2][128][20];
    __shared__ uint32_t Bs[2][BN][20];

    const int tid = threadIdx.x, lane = tid & 31, wid = tid >> 5;
    const int wm = (wid >> 1) * 32, wn = (wid & 1) * (BN / 2);
    const int m0 = blockIdx.y * 128, n0 = blockIdx.x * BN;

    const int ar = tid >> 1;
    constexpr int TPB = 256 / BN;
    constexpr int BH  = 32 / TPB;
    const int br = tid / TPB;

    const TA* Ap = A + (size_t)(m0 + ar) * lda + (tid & 1) * 16;
    const float* Wp = W + (size_t)(n0 + br) * K + (tid % TPB) * BH;

    float4 paf[4], pbf[BH / 4];
    uint4  pah[2];

    auto loadA = [&](int k0) {
        if constexpr (sizeof(TA) == 4) {
            const float* p = (const float*)Ap + k0;
            #pragma unroll
            for (int i = 0; i < 4; i++) paf[i] = *(const float4*)(p + i * 4);
        } else {
            const __half* p = (const __half*)Ap + k0;
            pah[0] = *(const uint4*)p;
            pah[1] = *(const uint4*)(p + 8);
        }
    };
    auto storeA = [&](int s) {
        uint32_t* d = &As[s][ar][(tid & 1) * 8];
        if constexpr (sizeof(TA) == 4) {
            #pragma unroll
            for (int i = 0; i < 4; i++) {
                d[2 * i]     = f2h2(paf[i].x, paf[i].y);
                d[2 * i + 1] = f2h2(paf[i].z, paf[i].w);
            }
        } else {
            *(uint4*)d = pah[0];
            *(uint4*)(d + 4) = pah[1];
        }
    };
    auto loadB = [&](int k0) {
        const float* p = Wp + k0;
        #pragma unroll
        for (int i = 0; i < BH / 4; i++) pbf[i] = *(const float4*)(p + i * 4);
    };
    auto storeB = [&](int s) {
        uint32_t* d = &Bs[s][br][(tid % TPB) * (BH / 2)];
        #pragma unroll
        for (int i = 0; i < BH / 4; i++) {
            d[2 * i]     = f2h2(pbf[i].x, pbf[i].y);
            d[2 * i + 1] = f2h2(pbf[i].z, pbf[i].w);
        }
    };

    float acc[2][NF][4] = {};
    loadA(0); loadB(0);

    const int nk = K >> 5;
    for (int t = 0; t < nk; t++) {
        const int s = t & 1;
        storeA(s); storeB(s);
        if (t + 1 < nk) { loadA((t + 1) * 32); loadB((t + 1) * 32); }
        __syncthreads();

        #pragma unroll
        for (int kk = 0; kk < 2; kk++) {
            uint32_t a[2][4];
            const int c = kk * 8 + (lane & 3);
            #pragma unroll
            for (int mi = 0; mi < 2; mi++) {
                const int r = wm + mi * 16 + (lane >> 2);
                a[mi][0] = As[s][r][c];     a[mi][1] = As[s][r + 8][c];
                a[mi][2] = As[s][r][c + 4]; a[mi][3] = As[s][r + 8][c + 4];
            }
            #pragma unroll
            for (int ni = 0; ni < NF; ni++) {
                const int n = wn + ni * 8 + (lane >> 2);
                uint32_t b0 = Bs[s][n][c], b1 = Bs[s][n][c + 4];
                #pragma unroll
                for (int mi = 0; mi < 2; mi++)
                    mma_f16(acc[mi][ni], a[mi], b0, b1);
            }
        }
    }

    #pragma unroll
    for (int mi = 0; mi < 2; mi++) {
        #pragma unroll
        for (int ni = 0; ni < NF; ni++) {
            const int r = m0 + wm + mi * 16 + (lane >> 2);
            const int c = n0 + wn + ni * 8 + 2 * (lane & 3);
            float b0 = bias ? bias[c] : 0.0f;
            float b1 = bias ? bias[c + 1] : 0.0f;
            float v0 = acc[mi][ni][0] + b0, v1 = acc[mi][ni][1] + b1;
            float v2 = acc[mi][ni][2] + b0, v3 = acc[mi][ni][3] + b1;
            if (c < scale_cols) { v0 *= qs; v1 *= qs; v2 *= qs; v3 *= qs; }
            if constexpr (sizeof(TC) == 2) {
                *(__half2*)&C[(size_t)r * ldc + c]       = __floats2half2_rn(v0, v1);
                *(__half2*)&C[(size_t)(r + 8) * ldc + c] = __floats2half2_rn(v2, v3);
            } else {
                *(float2*)&C[(size_t)r * ldc + c]       = make_float2(v0, v1);
                *(float2*)&C[(size_t)(r + 8) * ldc + c] = make_float2(v2, v3);
            }
        }
    }
}

// ---------------------------------------------------------------------------
// fp16 TN GEMM (for S): Sp[z][e][d] = sum_m inch[b][m][e] * attnph[b][m][d]
// (R14 version, unchanged)
// ---------------------------------------------------------------------------
__global__ __launch_bounds__(256, 3) void sgemm_tn_h(
    const __half* __restrict__ inch, const __half* __restrict__ Bh,
    float* __restrict__ Sp)
{
    __shared__ uint32_t As[2][32][68];   // [m][e-pairs]
    __shared__ uint32_t Bs[2][32][36];   // [m][d-pairs]

    const int tid = threadIdx.x, lane = tid & 31, wid = tid >> 5;
    const int wm = (wid >> 1) * 32, wn = (wid & 1) * 32;
    const int z = blockIdx.z, bz = z >> 2, sp = z & 3;
    const int e0 = blockIdx.y * 128, d0 = blockIdx.x * 64;
    const __half* Ab = inch + (size_t)bz * MM * EE + (size_t)(sp * 512) * EE;
    const __half* Bb = Bh   + (size_t)bz * MM * DD + (size_t)(sp * 512) * DD;

    const int am = tid >> 3;
    const __half* Apt = Ab + (size_t)am * EE + e0 + (tid & 7) * 16;
    const __half* Bpt = Bb + (size_t)am * DD + d0 + (tid & 7) * 8;

    uint4 pa0, pa1, pb;
    auto loadT = [&](int k0) {
        const __half* p = Apt + (size_t)k0 * EE;
        pa0 = *(const uint4*)p;
        pa1 = *(const uint4*)(p + 8);
        pb  = *(const uint4*)(Bpt + (size_t)k0 * DD);
    };
    auto storeT = [&](int s) {
        uint32_t* da = &As[s][am][(tid & 7) * 8];
        *(uint4*)da       = pa0;
        *(uint4*)(da + 4) = pa1;
        *(uint4*)&Bs[s][am][(tid & 7) * 4] = pb;
    };

    const uint32_t asb = smem_u32(As), bsb = smem_u32(Bs);

    float acc[2][4][4] = {};
    loadT(0);

    for (int t = 0; t < 16; t++) {   // 512 / 32
        const int s = t & 1;
        storeT(s);
        if (t + 1 < 16) loadT((t + 1) * 32);
        __syncthreads();

        #pragma unroll
        for (int kk = 0; kk < 2; kk++) {
            uint32_t a[2][4];
            #pragma unroll
            for (int mi = 0; mi < 2; mi++) {
                const int mrow = kk * 16 + (lane & 7) + ((lane & 16) >> 1);
                const int ecol = wm + mi * 16 + (lane & 8);
                uint32_t addr = asb + (((s * 32 + mrow) * 68 + (ecol >> 1)) << 2);
                ldsm4t(a[mi], addr);
            }
            #pragma unroll
            for (int ni = 0; ni < 4; ni++) {
                const int mrow = kk * 16 + (lane & 15);
                uint32_t addr = bsb + (((s * 32 + mrow) * 36 + (wn >> 1) + ni * 4) << 2);
                uint32_t b0, b1;
                ldsm2t(b0, b1, addr);
                #pragma unroll
                for (int mi = 0; mi < 2; mi++)
                    mma_f16(acc[mi][ni], a[mi], b0, b1);
            }
        }
    }

    float* Sb = Sp + (size_t)z * EE * DD;
    #pragma unroll
    for (int mi = 0; mi < 2; mi++) {
        #pragma unroll
        for (int ni = 0; ni < 4; ni++) {
            const int e = e0 + wm + mi * 16 + (lane >> 2);
            const int d = d0 + wn + ni * 8 + 2 * (lane & 3);
            *(float2*)&Sb[(size_t)e * DD + d] =
                make_float2(acc[mi][ni][0], acc[mi][ni][1]);
            *(float2*)&Sb[(size_t)(e + 8) * DD + d] =
                make_float2(acc[mi][ni][2], acc[mi][ni][3]);
        }
    }
}

// Reduce 4 split-K partials ordered [b][sp]: S[b] = sum_sp Sp[b*4+sp]
__global__ __launch_bounds__(256) void reduce4(
    const float4* __restrict__ Sp, float4* __restrict__ S)
{
    const size_t per = (size_t)EE * DD / 4;
    size_t i = (size_t)blockIdx.x * 256 + threadIdx.x;
    if (i >= (size_t)BB * per) return;
    size_t b = i / per, j = i - b * per;
    const float4* p = Sp + 4 * b * per + j;
    float4 a = p[0], x = p[per], y = p[2 * per], w = p[3 * per];
    float4 r;
    r.x = (a.x + x.x) + (y.x + w.x);
    r.y = (a.y + x.y) + (y.y + w.y);
    r.z = (a.z + x.z) + (y.z + w.z);
    r.w = (a.w + x.w) + (y.w + w.w);
    S[i] = r;
}

// ---------------------------------------------------------------------------
// Flash attention: fp16 in/out, base-2 softmax (bare MUFU.EX2), 128-key tiles,
// 3-stage cp.async ring, ONE __syncthreads per tile.
// 128 q-rows per block, 256 threads / 8 warps (16 q-rows each).
// Dynamic smem: Ks[3][128][20] + Vs[3][128][20] + Ps[128][68] = 96256 B.
// ---------------------------------------------------------------------------
#define FL_SMEM (3 * 128 * 20 * 4 * 2 + 128 * 68 * 4)

__global__ __launch_bounds__(256, 2) void flash_h(
    const __half* __restrict__ qkv, __half* __restrict__ o)
{
    extern __shared__ uint32_t dsm[];
    uint32_t* KsA = dsm;                    // [3][128][20]
    uint32_t* VsA = dsm + 3 * 128 * 20;     // [3][128][20]
    uint32_t* Ps  = VsA + 3 * 128 * 20;     // [128][68]; also Q staging scratch

    const int bh = blockIdx.y;
    const int b = bh >> 3, h = bh & 7;
    const int m0 = blockIdx.x * 128;
    const int tid = threadIdx.x;
    const int lane = tid & 31;
    const int w16 = (tid >> 5) * 16;

    const size_t base = (size_t)(b * MM) * TD + h * DH;
    const uint32_t ksb = smem_u32(KsA), vsb = smem_u32(VsA);

    // ---- stage Q (already scaled fp16) into Ps scratch (pitch 20 u32) ----
    {
        const int r = tid >> 1;
        const __half* qp = &qkv[base + (size_t)(m0 + r) * TD + (tid & 1) * 16];
        uint32_t* d = &Ps[r * 20 + (tid & 1) * 8];
        *(uint4*)d       = *(const uint4*)qp;
        *(uint4*)(d + 4) = *(const uint4*)(qp + 8);
    }
    __syncthreads();
    uint32_t qa[2][4];
    #pragma unroll
    for (int kk = 0; kk < 2; kk++) {
        const int r = w16 + (lane >> 2), c = kk * 8 + (lane & 3);
        qa[kk][0] = Ps[r * 20 + c];        qa[kk][1] = Ps[(r + 8) * 20 + c];
        qa[kk][2] = Ps[r * 20 + c + 4];    qa[kk][3] = Ps[(r + 8) * 20 + c + 4];
    }
    __syncthreads();

    float O[4][4] = {};
    float mr0 = -1e30f, mr1 = -1e30f, l0 = 0.0f, l1 = 0.0f;

    // K/V cp.async staging: rk = key row (0..63, plus +64), ck = 8 halves
    const int rk = tid >> 2, ck = (tid & 3) * 8;
    const uint32_t soff = (uint32_t)((rk * 20 + (tid & 3) * 4) * 4);

    auto stage = [&](int tile, int stg) {
        const __half* kp = &qkv[base + (size_t)(tile * 128 + rk) * TD + 256 + ck];
        const uint32_t ks0 = ksb + (uint32_t)(stg * 128 * 20 * 4) + soff;
        const uint32_t vs0 = vsb + (uint32_t)(stg * 128 * 20 * 4) + soff;
        cp16(ks0, kp);
        cp16(vs0, kp + 256);
        cp16(ks0 + 64 * 20 * 4, kp + (size_t)64 * TD);
        cp16(vs0 + 64 * 20 * 4, kp + (size_t)64 * TD + 256);
        CP_COMMIT();
    };

    stage(0, 0);
    stage(1, 1);

    const int ntile = MM / 128;   // 16
    for (int t = 0; t < ntile; t++) {
        const int stg = t % 3;
        if (t + 1 < ntile) CP_WAIT1(); else CP_WAIT0();
        __syncthreads();   // tile t visible; everyone done reading buf (t-1)%3
        if (t + 2 < ntile) stage(t + 2, (t + 2) % 3);

        const uint32_t kbase = (uint32_t)(stg * 128 * 20);

        // ---- S = Q @ K^T : 16 j-frags x 2 k16 ----
        float sa[16][4] = {};
        #pragma unroll
        for (int j = 0; j < 16; j++) {
            const int krow = j * 8 + (lane >> 2);
            #pragma unroll
            for (int kk = 0; kk < 2; kk++) {
                const int c = kk * 8 + (lane & 3);
                uint32_t b0 = KsA[kbase + krow * 20 + c];
                uint32_t b1 = KsA[kbase + krow * 20 + c + 4];
                mma_f16(sa[j], qa[kk], b0, b1);
            }
        }

        // ---- online softmax (base 2) over 128 keys ----
        float mx0 = -1e30f, mx1 = -1e30f;
        #pragma unroll
        for (int j = 0; j < 16; j++) {
            mx0 = fmaxf(mx0, fmaxf(sa[j][0], sa[j][1]));
            mx1 = fmaxf(mx1, fmaxf(sa[j][2], sa[j][3]));
        }
        mx0 = fmaxf(mx0, __shfl_xor_sync(0xFFFFFFFFu, mx0, 1));
        mx0 = fmaxf(mx0, __shfl_xor_sync(0xFFFFFFFFu, mx0, 2));
        mx1 = fmaxf(mx1, __shfl_xor_sync(0xFFFFFFFFu, mx1, 1));
        mx1 = fmaxf(mx1, __shfl_xor_sync(0xFFFFFFFFu, mx1, 2));

        float mn0 = fmaxf(mr0, mx0), mn1 = fmaxf(mr1, mx1);
        float al0 = ex2(mr0 - mn0), al1 = ex2(mr1 - mn1);
        mr0 = mn0; mr1 = mn1;

        float s0 = 0.0f, s1 = 0.0f;
        const int pr = w16 + (lane >> 2);
        #pragma unroll
        for (int j = 0; j < 16; j++) {
            float p00 = ex2(sa[j][0] - mn0);
            float p01 = ex2(sa[j][1] - mn0);
            float p10 = ex2(sa[j][2] - mn1);
            float p11 = ex2(sa[j][3] - mn1);
            s0 += p00 + p01; s1 += p10 + p11;
            const int pc = j * 4 + (lane & 3);
            Ps[pr * 68 + pc]       = f2h2(p00, p01);
            Ps[(pr + 8) * 68 + pc] = f2h2(p10, p11);
        }
        s0 += __shfl_xor_sync(0xFFFFFFFFu, s0, 1);
        s0 += __shfl_xor_sync(0xFFFFFFFFu, s0, 2);
        s1 += __shfl_xor_sync(0xFFFFFFFFu, s1, 1);
        s1 += __shfl_xor_sync(0xFFFFFFFFu, s1, 2);
        l0 = l0 * al0 + s0;
        l1 = l1 * al1 + s1;
        #pragma unroll
        for (int ni = 0; ni < 4; ni++) {
            O[ni][0] *= al0; O[ni][1] *= al0;
            O[ni][2] *= al1; O[ni][3] *= al1;
        }
        __syncwarp();

        // ---- O += P @ V : 8 k16 chunks x 4 n-frags ----
        #pragma unroll
        for (int kc = 0; kc < 8; kc++) {
            uint32_t pa[4];
            const int c = kc * 8 + (lane & 3);
            pa[0] = Ps[pr * 68 + c];       pa[1] = Ps[(pr + 8) * 68 + c];
            pa[2] = Ps[pr * 68 + c + 4];   pa[3] = Ps[(pr + 8) * 68 + c + 4];
            const int vrow = kc * 16 + (lane & 15);
            #pragma unroll
            for (int ni = 0; ni < 4; ni++) {
                uint32_t addr = vsb + ((stg * 128 + vrow) * 20 + ni * 4) * 4;
                uint32_t b0, b1;
                ldsm2t(b0, b1, addr);
                mma_f16(O[ni], pa, b0, b1);
            }
        }
        // no trailing sync: next tile's cp.async is issued only after the
        // __syncthreads at the top of the next iteration (reuse distance 3).
    }

    const float inv0 = 1.0f / l0, inv1 = 1.0f / l1;
    #pragma unroll
    for (int ni = 0; ni < 4; ni++) {
        const int row = m0 + w16 + (lane >> 2);
        const int col = h * DH + ni * 8 + 2 * (lane & 3);
        size_t off = ((size_t)(b * MM) + row) * DD + col;
        *(__half2*)&o[off] = __floats2half2_rn(O[ni][0] * inv0, O[ni][1] * inv0);
        *(__half2*)&o[off + 8 * DD] =
            __floats2half2_rn(O[ni][2] * inv1, O[ni][3] * inv1);
    }
}

// ---------------------------------------------------------------------------
// Column softmax over e + multiply:  ef = half(S * softmax_e(S))
// ---------------------------------------------------------------------------
__global__ __launch_bounds__(256) void col_softmax_mul(
    const float* __restrict__ S, __half* __restrict__ ef)
{
    const int b  = blockIdx.y;
    const int d0 = blockIdx.x * 64;
    const int dx = threadIdx.x & 63, ry = threadIdx.x >> 6;
    const float* Sb = S  + (size_t)b * EE * DD + d0 + dx;
    __half*      Eb = ef + (size_t)b * EE * DD + d0 + dx;

    __shared__ float red[4][64];

    float m = -1e30f;
    for (int e = ry; e < EE; e += 4) m = fmaxf(m, Sb[(size_t)e * DD]);
    red[ry][dx] = m;
    __syncthreads();
    m = fmaxf(fmaxf(red[0][dx], red[1][dx]), fmaxf(red[2][dx], red[3][dx]));
    __syncthreads();

    float s = 0.0f;
    for (int e = ry; e < EE; e += 4) s += __expf(Sb[(size_t)e * DD] - m);
    red[ry][dx] = s;
    __syncthreads();
    s = red[0][dx] + red[1][dx] + red[2][dx] + red[3][dx];
    float inv = 1.0f / s;

    for (int e = ry; e < EE; e += 4) {
        float v = Sb[(size_t)e * DD];
        Eb[(size_t)e * DD] = __float2half(v * __expf(v - m) * inv);
    }
}

// ---------------------------------------------------------------------------
// LayerNorm (dim 256) + residual mix:  out = (1+alpha)*prev + (1-alpha)*LN(x)
// ---------------------------------------------------------------------------
__global__ __launch_bounds__(256) void ln_res(
    const float* __restrict__ ef2, const float* __restrict__ prev,
    const float* __restrict__ gamma, const float* __restrict__ beta,
    const float* __restrict__ alphap, float* __restrict__ out)
{
    const int row = blockIdx.x;
    const int c = threadIdx.x;
    const size_t off = (size_t)row * DD + c;

    float x = ef2[off];
    float s = x, q = x * x;
    #pragma unroll
    for (int o2 = 16; o2 > 0; o2 >>= 1) {
        s += __shfl_down_sync(0xFFFFFFFFu, s, o2);
        q += __shfl_down_sync(0xFFFFFFFFu, q, o2);
    }
    __shared__ float rs[8], rq[8], mv[2];
    int w = c >> 5, l = c & 31;
    if (l == 0) { rs[w] = s; rq[w] = q; }
    __syncthreads();
    if (c == 0) {
        float S2 = 0.0f, Q2 = 0.0f;
        #pragma unroll
        for (int i = 0; i < 8; i++) { S2 += rs[i]; Q2 += rq[i]; }
        float mean = S2 * (1.0f / 256.0f);
        float var  = Q2 * (1.0f / 256.0f) - mean * mean;
        mv[0] = mean;
        mv[1] = rsqrtf(var + 1e-5f);
    }
    __syncthreads();

    float n = (x - mv[0]) * mv[1] * gamma[c] + beta[c];
    float a = *alphap;
    float p = prev[off];
    out[off] = (1.0f + a) * p + (1.0f - a) * n;
}

// ---------------------------------------------------------------------------
// Launch
// ---------------------------------------------------------------------------
extern "C" void kernel_launch(void* const* d_in, const int* in_sizes, int n_in,
                              void* d_out, int out_size)
{
    const float* feat = (const float*)d_in[0];
    const float* inc  = (const float*)d_in[1];
    const float* prev = (const float*)d_in[2];
    const float* ipw  = (const float*)d_in[3];
    const float* ipb  = (const float*)d_in[4];
    const float* opw  = (const float*)d_in[5];
    const float* opb  = (const float*)d_in[6];
    const float* pw   = (const float*)d_in[7];
    const float* gam  = (const float*)d_in[8];
    const float* bet  = (const float*)d_in[9];
    const float* alp  = (const float*)d_in[10];
    float* out = (float*)d_out;

    __half *qkvh, *attnh, *attnph, *inch, *efh;
    float *Sp, *Sb, *ef2;
    cudaGetSymbolAddress((void**)&qkvh,   g_qkvh);
    cudaGetSymbolAddress((void**)&attnh,  g_attnh);
    cudaGetSymbolAddress((void**)&attnph, g_attnph);
    cudaGetSymbolAddress((void**)&inch,   g_inch);
    cudaGetSymbolAddress((void**)&Sp,     g_Sp);
    cudaGetSymbolAddress((void**)&Sb,     g_S);
    cudaGetSymbolAddress((void**)&efh,    g_efh);
    cudaGetSymbolAddress((void**)&ef2,    g_ef2);

    // 1/sqrt(32) * log2(e): base-2 softmax absorbed into Q scaling
    const float qscale = 0.17677669529663689f * 1.4426950408889634f;

    // 0. convert inc -> fp16 (8 elems/thread)
    {
        const int n8 = BB * MM * EE / 8;
        f2h_bulk<<<(n8 + 255) / 256, 256>>>((const float4*)inc,
                                            (uint4*)inch, n8);
    }

    // 1. QKV projection -> fp16, Q third pre-scaled
    hgemm_nt<128, float, __half>
        <<<dim3(TD / 128, (BB * MM) / 128), 256>>>(
            feat, ipw, ipb, qkvh, DD, DD, TD, DD, qscale);

    // 2. flash attention (128-key tiles, cp.async 3-stage ring)
    cudaFuncSetAttribute(flash_h, cudaFuncAttributeMaxDynamicSharedMemorySize,
                         FL_SMEM);
    flash_h<<<dim3(MM / 128, BB * HH), 256, FL_SMEM>>>(qkvh, attnh);

    // 3. out projection -> fp16 attnph
    hgemm_nt<64, __half, __half>
        <<<dim3(DD / 64, (BB * MM) / 128), 256>>>(
            attnh, opw, opb, attnph, DD, DD, DD, 0, 1.0f);

    // 4. S = inch^T @ attnph  (TN fp16, split-K x4) + reduce
    sgemm_tn_h<<<dim3(DD / 64, EE / 128, BB * 4), 256>>>(inch, attnph, Sp);
    reduce4<<<(BB * EE * DD / 4 + 255) / 256, 256>>>((const float4*)Sp,
                                                     (float4*)Sb);

    // 5. ef = half(S * softmax_e(S))
    col_softmax_mul<<<dim3(DD / 64, BB), 256>>>(Sb, efh);

    // 6. ef2 = ef @ proj_w^T
    hgemm_nt<64, __half, float>
        <<<dim3(DD / 64, (BB * EE) / 128), 256>>>(
            efh, pw, nullptr, ef2, DD, DD, DD, 0, 1.0f);

    // 7. LayerNorm + residual mix
    ln_res<<<BB * EE, 256>>>(ef2, prev, gam, bet, alp, out);
}